// round 1
// baseline (speedup 1.0000x reference)
#include <cuda_runtime.h>
#include <cuda_bf16.h>
#include <math.h>

#define BSZ 16
#define SEQ 256
#define HID 768
#define TOK (BSZ*SEQ)      // 4096
#define FFN 3072
#define NH 12
#define HD 64
#define NT 9
#define NLAYERS 6

// ---------------- scratch (static device globals; no allocations) ----------------
__device__ float g_x[TOK*HID];
__device__ float g_h1[TOK*HID];
__device__ float g_tmp[TOK*HID];
__device__ float g_qkv[TOK*3*HID];
__device__ float g_attn[TOK*HID];
__device__ float g_ffn[(size_t)TOK*FFN];
__device__ float g_logits[TOK*NT];
__device__ float g_res[BSZ];

// ---------------- reductions ----------------
__device__ __forceinline__ float warpReduceSum(float v){
    #pragma unroll
    for (int o = 16; o; o >>= 1) v += __shfl_xor_sync(0xffffffffu, v, o);
    return v;
}
__device__ __forceinline__ float warpReduceMax(float v){
    #pragma unroll
    for (int o = 16; o; o >>= 1) v = fmaxf(v, __shfl_xor_sync(0xffffffffu, v, o));
    return v;
}
// blockDim.x must be multiple of 32, <= 1024
__device__ float blockReduceSum(float v, float* sh){
    __syncthreads();
    int lane = threadIdx.x & 31, wid = threadIdx.x >> 5;
    v = warpReduceSum(v);
    if (lane == 0) sh[wid] = v;
    __syncthreads();
    int nw = blockDim.x >> 5;
    v = (threadIdx.x < nw) ? sh[threadIdx.x] : 0.0f;
    if (wid == 0) v = warpReduceSum(v);
    if (threadIdx.x == 0) sh[0] = v;
    __syncthreads();
    return sh[0];
}
__device__ float blockReduceMax(float v, float* sh){
    __syncthreads();
    int lane = threadIdx.x & 31, wid = threadIdx.x >> 5;
    v = warpReduceMax(v);
    if (lane == 0) sh[wid] = v;
    __syncthreads();
    int nw = blockDim.x >> 5;
    v = (threadIdx.x < nw) ? sh[threadIdx.x] : -INFINITY;
    if (wid == 0) v = warpReduceMax(v);
    if (threadIdx.x == 0) sh[0] = v;
    __syncthreads();
    return sh[0];
}

__device__ __forceinline__ float gelu_tanh(float x){
    float x3 = x * x * x;
    return 0.5f * x * (1.0f + tanhf(0.7978845608028654f * (x + 0.044715f * x3)));
}

// ---------------- embedding + LN ----------------
// one block per token, 256 threads, 3 elems/thread
__global__ void embed_kernel(const int* __restrict__ ids,
                             const float* __restrict__ we,
                             const float* __restrict__ pe,
                             const float* __restrict__ gamma,
                             const float* __restrict__ beta,
                             float* __restrict__ out){
    __shared__ float sh[32];
    int tok = blockIdx.x;
    int sI = tok % SEQ;
    int id = ids[tok];
    const float* wrow = we + (size_t)id * HID;
    const float* prow = pe + (size_t)sI * HID;
    float vals[3]; float lsum = 0.f;
    #pragma unroll
    for (int i = 0; i < 3; i++){
        int d = threadIdx.x + i * 256;
        float v = wrow[d] + prow[d];
        vals[i] = v; lsum += v;
    }
    float mean = blockReduceSum(lsum, sh) * (1.0f / HID);
    float lss = 0.f;
    #pragma unroll
    for (int i = 0; i < 3; i++){ float d0 = vals[i] - mean; lss += d0 * d0; }
    float var = blockReduceSum(lss, sh) * (1.0f / HID);
    float rstd = rsqrtf(var + 1e-12f);
    float* orow = out + (size_t)tok * HID;
    #pragma unroll
    for (int i = 0; i < 3; i++){
        int d = threadIdx.x + i * 256;
        orow[d] = (vals[i] - mean) * rstd * gamma[d] + beta[d];
    }
}

// ---------------- residual + LN : out = LN(a + c) ----------------
__global__ void ln_residual_kernel(const float* __restrict__ a,
                                   const float* __restrict__ c,
                                   const float* __restrict__ gamma,
                                   const float* __restrict__ beta,
                                   float* __restrict__ out){
    __shared__ float sh[32];
    int tok = blockIdx.x;
    const float* ar = a + (size_t)tok * HID;
    const float* cr = c + (size_t)tok * HID;
    float vals[3]; float lsum = 0.f;
    #pragma unroll
    for (int i = 0; i < 3; i++){
        int d = threadIdx.x + i * 256;
        float v = ar[d] + cr[d];
        vals[i] = v; lsum += v;
    }
    float mean = blockReduceSum(lsum, sh) * (1.0f / HID);
    float lss = 0.f;
    #pragma unroll
    for (int i = 0; i < 3; i++){ float d0 = vals[i] - mean; lss += d0 * d0; }
    float var = blockReduceSum(lss, sh) * (1.0f / HID);
    float rstd = rsqrtf(var + 1e-12f);
    float* orow = out + (size_t)tok * HID;
    #pragma unroll
    for (int i = 0; i < 3; i++){
        int d = threadIdx.x + i * 256;
        orow[d] = (vals[i] - mean) * rstd * gamma[d] + beta[d];
    }
}

// ---------------- tiled fp32 GEMM:  C[M,N] = A[M,K] @ W[K,N] + bias (opt gelu) --------
// BM=BN=64, BK=16, 16x16 threads, 4x4 per thread. All dims divisible.
__global__ void gemm_kernel(const float* __restrict__ A,
                            const float* __restrict__ W,
                            const float* __restrict__ bias,
                            float* __restrict__ C,
                            int M, int N, int K, int act){
    __shared__ float As[16][65];
    __shared__ float Ws[16][64];
    int tid = threadIdx.y * 16 + threadIdx.x;
    int rowBase = blockIdx.y * 64;
    int colBase = blockIdx.x * 64;
    float acc[4][4] = {};
    for (int k0 = 0; k0 < K; k0 += 16){
        #pragma unroll
        for (int i = 0; i < 4; i++){
            int r = (tid >> 4) + i * 16;
            int c = tid & 15;
            As[c][r] = A[(size_t)(rowBase + r) * K + k0 + c];
        }
        #pragma unroll
        for (int i = 0; i < 4; i++){
            int r = (tid >> 6) + i * 4;
            int c = tid & 63;
            Ws[r][c] = W[(size_t)(k0 + r) * N + colBase + c];
        }
        __syncthreads();
        #pragma unroll
        for (int kk = 0; kk < 16; kk++){
            float a[4], w[4];
            #pragma unroll
            for (int i = 0; i < 4; i++) a[i] = As[kk][threadIdx.y * 4 + i];
            #pragma unroll
            for (int j = 0; j < 4; j++) w[j] = Ws[kk][threadIdx.x * 4 + j];
            #pragma unroll
            for (int i = 0; i < 4; i++)
                #pragma unroll
                for (int j = 0; j < 4; j++)
                    acc[i][j] = fmaf(a[i], w[j], acc[i][j]);
        }
        __syncthreads();
    }
    #pragma unroll
    for (int i = 0; i < 4; i++){
        int r = rowBase + threadIdx.y * 4 + i;
        #pragma unroll
        for (int j = 0; j < 4; j++){
            int c = colBase + threadIdx.x * 4 + j;
            float v = acc[i][j] + bias[c];
            if (act == 1) v = gelu_tanh(v);
            C[(size_t)r * N + c] = v;
        }
    }
}

// ---------------- attention: one block per (sq, h, b), 256 threads ----------------
__global__ void attn_kernel(const float* __restrict__ qkv,
                            const int* __restrict__ amask,
                            float* __restrict__ out){
    __shared__ float q[HD];
    __shared__ float p[SEQ];
    __shared__ float sh[32];
    int sq = blockIdx.x, h = blockIdx.y, b = blockIdx.z;
    size_t rowQ = ((size_t)(b * SEQ + sq)) * (3 * HID) + h * HD;
    if (threadIdx.x < HD) q[threadIdx.x] = qkv[rowQ + threadIdx.x];
    __syncthreads();
    int k = threadIdx.x;
    const float* kp = qkv + ((size_t)(b * SEQ + k)) * (3 * HID) + HID + h * HD;
    float sc = 0.f;
    #pragma unroll 16
    for (int d = 0; d < HD; d++) sc = fmaf(q[d], kp[d], sc);
    sc *= 0.125f;
    sc += (1.0f - (float)amask[b * SEQ + k]) * -1e9f;
    float m = blockReduceMax(sc, sh);
    float e = expf(sc - m);
    float s = blockReduceSum(e, sh);
    p[k] = e / s;
    __syncthreads();
    if (threadIdx.x < HD){
        int d = threadIdx.x;
        const float* vb = qkv + (size_t)b * SEQ * (3 * HID) + 2 * HID + h * HD + d;
        float acc = 0.f;
        #pragma unroll 8
        for (int kk = 0; kk < SEQ; kk++)
            acc = fmaf(p[kk], vb[(size_t)kk * (3 * HID)], acc);
        out[((size_t)(b * SEQ + sq)) * HID + h * HD + d] = acc;
    }
}

// ---------------- classifier: logits = x @ Wcls + bcls  (N=9) ----------------
// one block per token, 288 threads = 9 warps (one warp per tag)
__global__ void cls_kernel(const float* __restrict__ x,
                           const float* __restrict__ W,
                           const float* __restrict__ bias,
                           float* __restrict__ logits){
    __shared__ float xs[HID];
    int tok = blockIdx.x;
    for (int d = threadIdx.x; d < HID; d += blockDim.x)
        xs[d] = x[(size_t)tok * HID + d];
    __syncthreads();
    int w = threadIdx.x >> 5, lane = threadIdx.x & 31;
    float acc = 0.f;
    for (int d = lane; d < HID; d += 32)
        acc = fmaf(xs[d], W[d * NT + w], acc);
    acc = warpReduceSum(acc);
    if (lane == 0) logits[tok * NT + w] = acc + bias[w];
}

// ---------------- CRF: one block (32 threads) per batch element ----------------
__global__ void crf_kernel(const float* __restrict__ logits,
                           const int* __restrict__ labels,
                           const float* __restrict__ cstart,
                           const float* __restrict__ cend,
                           const float* __restrict__ ctrans,
                           float* __restrict__ res){
    __shared__ float score[NT];
    __shared__ float tr[NT * NT];
    __shared__ float st[NT], en[NT];
    int b = blockIdx.x, tid = threadIdx.x;
    for (int i = tid; i < NT * NT; i += 32) tr[i] = ctrans[i];
    if (tid < NT){ st[tid] = cstart[tid]; en[tid] = cend[tid]; }
    const float* lg = logits + (size_t)b * SEQ * NT;
    const int* lab = labels + b * SEQ;
    if (tid < NT) score[tid] = st[tid] + lg[tid];
    __syncwarp();
    for (int s = 1; s < SEQ; s++){
        float nxt = 0.f;
        if (tid < NT){
            float m = -INFINITY;
            #pragma unroll
            for (int i = 0; i < NT; i++) m = fmaxf(m, score[i] + tr[i * NT + tid]);
            float sum = 0.f;
            #pragma unroll
            for (int i = 0; i < NT; i++) sum += expf(score[i] + tr[i * NT + tid] - m);
            nxt = m + logf(sum) + lg[s * NT + tid];
        }
        bool msk = (lab[s] != -100);
        __syncwarp();
        if (tid < NT && msk) score[tid] = nxt;
        __syncwarp();
    }
    if (tid == 0){
        // denominator
        float m = -INFINITY;
        for (int t = 0; t < NT; t++) m = fmaxf(m, score[t] + en[t]);
        float sum = 0.f;
        for (int t = 0; t < NT; t++) sum += expf(score[t] + en[t] - m);
        float denom = m + logf(sum);
        // numerator
        int l0 = lab[0];
        int tag_prev = (l0 == -100) ? 0 : l0;
        float num = st[tag_prev] + lg[tag_prev];
        int cnt = 1; // mask[:,0] forced true
        for (int s = 1; s < SEQ; s++){
            int ls = lab[s];
            bool msk = (ls != -100);
            int tg = msk ? ls : 0;
            if (msk){
                num += tr[tag_prev * NT + tg] + lg[s * NT + tg];
                cnt++;
            }
            tag_prev = tg;
        }
        int seq_end = cnt - 1;
        int le = lab[seq_end];
        int last_tag = (le == -100) ? 0 : le;
        num += en[last_tag];
        res[b] = num - denom;
    }
}

// ---------------- finalize: d_out[0]=loss, d_out[1..]=logits ----------------
__global__ void finalize_kernel(const float* __restrict__ res,
                                const float* __restrict__ logits,
                                float* __restrict__ out, int nlog){
    int idx = blockIdx.x * blockDim.x + threadIdx.x;
    if (idx == 0){
        float s = 0.f;
        for (int b = 0; b < BSZ; b++) s += res[b];
        out[0] = -s / BSZ;
    }
    if (idx < nlog) out[1 + idx] = logits[idx];
}

// ---------------- launch ----------------
extern "C" void kernel_launch(void* const* d_in, const int* in_sizes, int n_in,
                              void* d_out, int out_size){
    const int*   input_ids = (const int*)  d_in[0];
    const int*   amask     = (const int*)  d_in[1];
    const int*   labels    = (const int*)  d_in[2];
    const float* word_emb  = (const float*)d_in[3];
    const float* pos_emb   = (const float*)d_in[4];
    const float* emb_ln_s  = (const float*)d_in[5];
    const float* emb_ln_b  = (const float*)d_in[6];
    const float* Wqkv      = (const float*)d_in[7];
    const float* bqkv      = (const float*)d_in[8];
    const float* Wo        = (const float*)d_in[9];
    const float* bo        = (const float*)d_in[10];
    const float* ln1_s     = (const float*)d_in[11];
    const float* ln1_b     = (const float*)d_in[12];
    const float* Wff1      = (const float*)d_in[13];
    const float* bff1      = (const float*)d_in[14];
    const float* Wff2      = (const float*)d_in[15];
    const float* bff2      = (const float*)d_in[16];
    const float* ln2_s     = (const float*)d_in[17];
    const float* ln2_b     = (const float*)d_in[18];
    const float* Wcls      = (const float*)d_in[19];
    const float* bcls      = (const float*)d_in[20];
    const float* crf_start = (const float*)d_in[21];
    const float* crf_end   = (const float*)d_in[22];
    const float* crf_trans = (const float*)d_in[23];

    float *x, *h1, *tmp, *qkv, *attn, *ffn, *logits, *res;
    cudaGetSymbolAddress((void**)&x,      g_x);
    cudaGetSymbolAddress((void**)&h1,     g_h1);
    cudaGetSymbolAddress((void**)&tmp,    g_tmp);
    cudaGetSymbolAddress((void**)&qkv,    g_qkv);
    cudaGetSymbolAddress((void**)&attn,   g_attn);
    cudaGetSymbolAddress((void**)&ffn,    g_ffn);
    cudaGetSymbolAddress((void**)&logits, g_logits);
    cudaGetSymbolAddress((void**)&res,    g_res);

    dim3 tb16(16, 16);

    // embedding + LN
    embed_kernel<<<TOK, 256>>>(input_ids, word_emb, pos_emb, emb_ln_s, emb_ln_b, x);

    for (int l = 0; l < NLAYERS; l++){
        const float* wqkv = Wqkv + (size_t)l * HID * 3 * HID;
        const float* bq   = bqkv + (size_t)l * 3 * HID;
        const float* wo   = Wo   + (size_t)l * HID * HID;
        const float* bo_  = bo   + (size_t)l * HID;
        const float* s1   = ln1_s + (size_t)l * HID;
        const float* b1   = ln1_b + (size_t)l * HID;
        const float* w1   = Wff1 + (size_t)l * HID * FFN;
        const float* bf1  = bff1 + (size_t)l * FFN;
        const float* w2   = Wff2 + (size_t)l * FFN * HID;
        const float* bf2  = bff2 + (size_t)l * HID;
        const float* s2   = ln2_s + (size_t)l * HID;
        const float* b2   = ln2_b + (size_t)l * HID;

        // QKV projection
        gemm_kernel<<<dim3(3 * HID / 64, TOK / 64), tb16>>>(x, wqkv, bq, qkv, TOK, 3 * HID, HID, 0);
        // attention
        attn_kernel<<<dim3(SEQ, NH, BSZ), 256>>>(qkv, amask, attn);
        // output projection
        gemm_kernel<<<dim3(HID / 64, TOK / 64), tb16>>>(attn, wo, bo_, tmp, TOK, HID, HID, 0);
        // h1 = LN(x + tmp)
        ln_residual_kernel<<<TOK, 256>>>(x, tmp, s1, b1, h1);
        // FFN1 + gelu
        gemm_kernel<<<dim3(FFN / 64, TOK / 64), tb16>>>(h1, w1, bf1, ffn, TOK, FFN, HID, 1);
        // FFN2
        gemm_kernel<<<dim3(HID / 64, TOK / 64), tb16>>>(ffn, w2, bf2, tmp, TOK, HID, FFN, 0);
        // x = LN(h1 + tmp)
        ln_residual_kernel<<<TOK, 256>>>(h1, tmp, s2, b2, x);
    }

    // classifier
    cls_kernel<<<TOK, 288>>>(x, Wcls, bcls, logits);
    // CRF per batch
    crf_kernel<<<BSZ, 32>>>(logits, labels, crf_start, crf_end, crf_trans, res);
    // finalize: loss + logits copy
    int nlog = TOK * NT;
    finalize_kernel<<<(nlog + 256) / 256, 256>>>(res, logits, (float*)d_out, nlog);
}

// round 2
// speedup vs baseline: 4.8969x; 4.8969x over previous
#include <cuda_runtime.h>
#include <cuda_bf16.h>
#include <math.h>
#include <stdint.h>

#define BSZ 16
#define SEQ 256
#define HID 768
#define TOK (BSZ*SEQ)      // 4096
#define FFN 3072
#define NH 12
#define HD 64
#define NT 9
#define NLAYERS 6

// ---------------- scratch (static device globals; no allocations) ----------------
__device__ float g_x[TOK*HID];
__device__ float g_h1[TOK*HID];
__device__ float g_tmp[TOK*HID];
__device__ float g_qkv[TOK*3*HID];
__device__ float g_attn[TOK*HID];
__device__ float g_ffn[(size_t)TOK*FFN];
__device__ float g_logits[TOK*NT];
__device__ float g_res[BSZ];

// ---------------- reductions ----------------
__device__ __forceinline__ float warpReduceSum(float v){
    #pragma unroll
    for (int o = 16; o; o >>= 1) v += __shfl_xor_sync(0xffffffffu, v, o);
    return v;
}
__device__ __forceinline__ float warpReduceMax(float v){
    #pragma unroll
    for (int o = 16; o; o >>= 1) v = fmaxf(v, __shfl_xor_sync(0xffffffffu, v, o));
    return v;
}
__device__ float blockReduceSum(float v, float* sh){
    __syncthreads();
    int lane = threadIdx.x & 31, wid = threadIdx.x >> 5;
    v = warpReduceSum(v);
    if (lane == 0) sh[wid] = v;
    __syncthreads();
    int nw = blockDim.x >> 5;
    v = (threadIdx.x < nw) ? sh[threadIdx.x] : 0.0f;
    if (wid == 0) v = warpReduceSum(v);
    if (threadIdx.x == 0) sh[0] = v;
    __syncthreads();
    return sh[0];
}

__device__ __forceinline__ float gelu_tanh(float x){
    float x3 = x * x * x;
    return 0.5f * x * (1.0f + tanhf(0.7978845608028654f * (x + 0.044715f * x3)));
}

// ---------------- tf32 helpers ----------------
__device__ __forceinline__ uint32_t f2tf32(float f){
    uint32_t r; asm("cvt.rna.tf32.f32 %0, %1;" : "=r"(r) : "f"(f)); return r;
}
__device__ __forceinline__ void mma_tf32(float* c, const uint32_t* a, const uint32_t* b){
    asm volatile(
        "mma.sync.aligned.m16n8k8.row.col.f32.tf32.tf32.f32 "
        "{%0,%1,%2,%3},{%4,%5,%6,%7},{%8,%9},{%0,%1,%2,%3};"
        : "+f"(c[0]), "+f"(c[1]), "+f"(c[2]), "+f"(c[3])
        : "r"(a[0]), "r"(a[1]), "r"(a[2]), "r"(a[3]), "r"(b[0]), "r"(b[1]));
}

// ---------------- embedding + LN ----------------
__global__ void embed_kernel(const int* __restrict__ ids,
                             const float* __restrict__ we,
                             const float* __restrict__ pe,
                             const float* __restrict__ gamma,
                             const float* __restrict__ beta,
                             float* __restrict__ out){
    __shared__ float sh[32];
    int tok = blockIdx.x;
    int sI = tok % SEQ;
    int id = ids[tok];
    const float* wrow = we + (size_t)id * HID;
    const float* prow = pe + (size_t)sI * HID;
    float vals[3]; float lsum = 0.f;
    #pragma unroll
    for (int i = 0; i < 3; i++){
        int d = threadIdx.x + i * 256;
        float v = wrow[d] + prow[d];
        vals[i] = v; lsum += v;
    }
    float mean = blockReduceSum(lsum, sh) * (1.0f / HID);
    float lss = 0.f;
    #pragma unroll
    for (int i = 0; i < 3; i++){ float d0 = vals[i] - mean; lss += d0 * d0; }
    float var = blockReduceSum(lss, sh) * (1.0f / HID);
    float rstd = rsqrtf(var + 1e-12f);
    float* orow = out + (size_t)tok * HID;
    #pragma unroll
    for (int i = 0; i < 3; i++){
        int d = threadIdx.x + i * 256;
        orow[d] = (vals[i] - mean) * rstd * gamma[d] + beta[d];
    }
}

// ---------------- residual + LN : out = LN(a + c) ----------------
__global__ void ln_residual_kernel(const float* __restrict__ a,
                                   const float* __restrict__ c,
                                   const float* __restrict__ gamma,
                                   const float* __restrict__ beta,
                                   float* __restrict__ out){
    __shared__ float sh[32];
    int tok = blockIdx.x;
    const float* ar = a + (size_t)tok * HID;
    const float* cr = c + (size_t)tok * HID;
    float vals[3]; float lsum = 0.f;
    #pragma unroll
    for (int i = 0; i < 3; i++){
        int d = threadIdx.x + i * 256;
        float v = ar[d] + cr[d];
        vals[i] = v; lsum += v;
    }
    float mean = blockReduceSum(lsum, sh) * (1.0f / HID);
    float lss = 0.f;
    #pragma unroll
    for (int i = 0; i < 3; i++){ float d0 = vals[i] - mean; lss += d0 * d0; }
    float var = blockReduceSum(lss, sh) * (1.0f / HID);
    float rstd = rsqrtf(var + 1e-12f);
    float* orow = out + (size_t)tok * HID;
    #pragma unroll
    for (int i = 0; i < 3; i++){
        int d = threadIdx.x + i * 256;
        orow[d] = (vals[i] - mean) * rstd * gamma[d] + beta[d];
    }
}

// ---------------- tf32 tensor-core GEMM: C[M,N] = A[M,K] @ W[K,N] + bias -------
// block tile 128x128, BK=32, 256 threads = 8 warps (4x2), warp tile 32x64
#define PA 4
#define PB 4
__global__ void gemm_tc(const float* __restrict__ A,
                        const float* __restrict__ W,
                        const float* __restrict__ bias,
                        float* __restrict__ C,
                        int M, int N, int K, int act){
    __shared__ float As[32][128 + PA];  // [k][m]
    __shared__ float Bs[32][128 + PB];  // [k][n]
    int tid = threadIdx.x;
    int wid = tid >> 5, lane = tid & 31;
    int warpRow = wid >> 1, warpCol = wid & 1;
    int gid = lane >> 2, tig = lane & 3;
    int rowBase = blockIdx.y * 128, colBase = blockIdx.x * 128;

    float acc[2][8][4];
    #pragma unroll
    for (int mi = 0; mi < 2; mi++)
        #pragma unroll
        for (int ni = 0; ni < 8; ni++)
            #pragma unroll
            for (int j = 0; j < 4; j++) acc[mi][ni][j] = 0.f;

    for (int k0 = 0; k0 < K; k0 += 32){
        // A tile (transpose to [k][m])
        #pragma unroll
        for (int i = 0; i < 4; i++){
            int m  = (tid >> 3) + i * 32;
            int kq = (tid & 7) * 4;
            float4 v = *(const float4*)(A + (size_t)(rowBase + m) * K + k0 + kq);
            As[kq + 0][m] = v.x; As[kq + 1][m] = v.y;
            As[kq + 2][m] = v.z; As[kq + 3][m] = v.w;
        }
        // B tile (direct [k][n])
        #pragma unroll
        for (int i = 0; i < 4; i++){
            int k  = (tid >> 5) + i * 8;
            int nq = (tid & 31) * 4;
            *(float4*)&Bs[k][nq] = *(const float4*)(W + (size_t)(k0 + k) * N + colBase + nq);
        }
        __syncthreads();
        #pragma unroll
        for (int ks = 0; ks < 4; ks++){
            int kb = ks * 8;
            uint32_t af[2][4], bf[8][2];
            #pragma unroll
            for (int mi = 0; mi < 2; mi++){
                int m0 = warpRow * 32 + mi * 16;
                af[mi][0] = f2tf32(As[kb + tig    ][m0 + gid    ]);
                af[mi][1] = f2tf32(As[kb + tig    ][m0 + gid + 8]);
                af[mi][2] = f2tf32(As[kb + tig + 4][m0 + gid    ]);
                af[mi][3] = f2tf32(As[kb + tig + 4][m0 + gid + 8]);
            }
            #pragma unroll
            for (int ni = 0; ni < 8; ni++){
                int n0 = warpCol * 64 + ni * 8;
                bf[ni][0] = f2tf32(Bs[kb + tig    ][n0 + gid]);
                bf[ni][1] = f2tf32(Bs[kb + tig + 4][n0 + gid]);
            }
            #pragma unroll
            for (int mi = 0; mi < 2; mi++)
                #pragma unroll
                for (int ni = 0; ni < 8; ni++)
                    mma_tf32(acc[mi][ni], af[mi], bf[ni]);
        }
        __syncthreads();
    }
    // epilogue
    #pragma unroll
    for (int mi = 0; mi < 2; mi++){
        int r0 = rowBase + warpRow * 32 + mi * 16 + gid;
        #pragma unroll
        for (int ni = 0; ni < 8; ni++){
            int cc = colBase + warpCol * 64 + ni * 8 + tig * 2;
            float b0 = bias[cc], b1 = bias[cc + 1];
            float v0 = acc[mi][ni][0] + b0, v1 = acc[mi][ni][1] + b1;
            float v2 = acc[mi][ni][2] + b0, v3 = acc[mi][ni][3] + b1;
            if (act == 1){
                v0 = gelu_tanh(v0); v1 = gelu_tanh(v1);
                v2 = gelu_tanh(v2); v3 = gelu_tanh(v3);
            }
            float2 p0 = make_float2(v0, v1);
            float2 p1 = make_float2(v2, v3);
            *(float2*)&C[(size_t)r0 * N + cc] = p0;
            *(float2*)&C[(size_t)(r0 + 8) * N + cc] = p1;
        }
    }
}

// ---------------- attention v2: flash-style, block = (128 queries, h, b) ------
// 256 threads = 8 warps; each warp owns 16 queries, processed 4 at a time.
// dyn smem: Qs[128][64] | Kt[64][64] (d-major) | Vs[64][64] | ps[8][4][64] | bs[256]
#define ATT_SMEM ((128*64 + 64*64 + 64*64 + 8*4*64 + 256) * 4)
__global__ void attn2_kernel(const float* __restrict__ qkv,
                             const int* __restrict__ amask,
                             float* __restrict__ out){
    extern __shared__ float sm[];
    float* Qs = sm;                  // 8192
    float* Kt = Qs + 128 * 64;       // 4096
    float* Vs = Kt + 64 * 64;        // 4096
    float* ps = Vs + 64 * 64;        // 2048
    float* bs = ps + 8 * 4 * 64;     // 256
    int tid = threadIdx.x, w = tid >> 5, lane = tid & 31;
    int qb = blockIdx.x * 128, h = blockIdx.y, b = blockIdx.z;
    const size_t rs = 3 * HID;
    const float* base = qkv + (size_t)b * SEQ * rs;

    bs[tid] = (1.0f - (float)amask[b * SEQ + tid]) * -1e9f;

    // load Q tile
    #pragma unroll
    for (int pass = 0; pass < 2; pass++){
        int q = (tid >> 2) + pass * 64;
        int d0 = (tid & 3) * 16;
        const float* src = base + (size_t)(qb + q) * rs + h * HD + d0;
        float* dst = Qs + q * 64 + d0;
        #pragma unroll
        for (int j = 0; j < 4; j++)
            *(float4*)(dst + j * 4) = *(const float4*)(src + j * 4);
    }

    float mJ[16], sJ[16], a0[16], a1[16];
    #pragma unroll
    for (int i = 0; i < 16; i++){ mJ[i] = -INFINITY; sJ[i] = 0.f; a0[i] = 0.f; a1[i] = 0.f; }

    for (int c = 0; c < 4; c++){
        __syncthreads();
        {   // load K chunk (transposed) + V chunk
            int k = tid >> 2;
            int d0 = (tid & 3) * 16;
            const float* ksrc = base + (size_t)(c * 64 + k) * rs + HID + h * HD + d0;
            const float* vsrc = base + (size_t)(c * 64 + k) * rs + 2 * HID + h * HD + d0;
            #pragma unroll
            for (int j = 0; j < 4; j++){
                float4 kv = *(const float4*)(ksrc + j * 4);
                Kt[(d0 + j * 4 + 0) * 64 + k] = kv.x;
                Kt[(d0 + j * 4 + 1) * 64 + k] = kv.y;
                Kt[(d0 + j * 4 + 2) * 64 + k] = kv.z;
                Kt[(d0 + j * 4 + 3) * 64 + k] = kv.w;
                *(float4*)(Vs + k * 64 + d0 + j * 4) = *(const float4*)(vsrc + j * 4);
            }
        }
        __syncthreads();

        #pragma unroll 1
        for (int ib = 0; ib < 4; ib++){     // 4 queries at a time
            int i0 = ib * 4;
            float sc[4][2];
            #pragma unroll
            for (int j = 0; j < 4; j++){ sc[j][0] = 0.f; sc[j][1] = 0.f; }
            const float* q0 = Qs + (w * 16 + i0) * 64;
            #pragma unroll 8
            for (int d = 0; d < 64; d++){
                float kt0 = Kt[d * 64 + lane];
                float kt1 = Kt[d * 64 + lane + 32];
                #pragma unroll
                for (int j = 0; j < 4; j++){
                    float qv = q0[j * 64 + d];
                    sc[j][0] = fmaf(qv, kt0, sc[j][0]);
                    sc[j][1] = fmaf(qv, kt1, sc[j][1]);
                }
            }
            float bm0 = bs[c * 64 + lane], bm1 = bs[c * 64 + lane + 32];
            #pragma unroll
            for (int j = 0; j < 4; j++){
                int i = i0 + j;
                float s0 = sc[j][0] * 0.125f + bm0;
                float s1 = sc[j][1] * 0.125f + bm1;
                float mx = warpReduceMax(fmaxf(s0, s1));
                float nm = fmaxf(mJ[i], mx);
                float e0 = __expf(s0 - nm), e1 = __expf(s1 - nm);
                float sumc = warpReduceSum(e0 + e1);
                float corr = __expf(mJ[i] - nm);
                sJ[i] = sJ[i] * corr + sumc;
                mJ[i] = nm;
                a0[i] *= corr; a1[i] *= corr;
                ps[(w * 4 + j) * 64 + lane] = e0;
                ps[(w * 4 + j) * 64 + lane + 32] = e1;
            }
            __syncwarp();
            float x0[4], x1[4];
            #pragma unroll
            for (int j = 0; j < 4; j++){ x0[j] = a0[i0 + j]; x1[j] = a1[i0 + j]; }
            #pragma unroll 4
            for (int k = 0; k < 64; k++){
                float v0 = Vs[k * 64 + lane];
                float v1 = Vs[k * 64 + lane + 32];
                #pragma unroll
                for (int j = 0; j < 4; j++){
                    float p = ps[(w * 4 + j) * 64 + k];
                    x0[j] = fmaf(p, v0, x0[j]);
                    x1[j] = fmaf(p, v1, x1[j]);
                }
            }
            #pragma unroll
            for (int j = 0; j < 4; j++){ a0[i0 + j] = x0[j]; a1[i0 + j] = x1[j]; }
            __syncwarp();
        }
    }
    #pragma unroll
    for (int i = 0; i < 16; i++){
        int q = qb + w * 16 + i;
        float inv = 1.0f / sJ[i];
        size_t o = (size_t)(b * SEQ + q) * HID + h * HD;
        out[o + lane]      = a0[i] * inv;
        out[o + lane + 32] = a1[i] * inv;
    }
}

// ---------------- classifier ----------------
__global__ void cls_kernel(const float* __restrict__ x,
                           const float* __restrict__ W,
                           const float* __restrict__ bias,
                           float* __restrict__ logits){
    __shared__ float xs[HID];
    int tok = blockIdx.x;
    for (int d = threadIdx.x; d < HID; d += blockDim.x)
        xs[d] = x[(size_t)tok * HID + d];
    __syncthreads();
    int w = threadIdx.x >> 5, lane = threadIdx.x & 31;
    float acc = 0.f;
    for (int d = lane; d < HID; d += 32)
        acc = fmaf(xs[d], W[d * NT + w], acc);
    acc = warpReduceSum(acc);
    if (lane == 0) logits[tok * NT + w] = acc + bias[w];
}

// ---------------- CRF ----------------
__global__ void crf_kernel(const float* __restrict__ logits,
                           const int* __restrict__ labels,
                           const float* __restrict__ cstart,
                           const float* __restrict__ cend,
                           const float* __restrict__ ctrans,
                           float* __restrict__ res){
    __shared__ float score[NT];
    __shared__ float tr[NT * NT];
    __shared__ float st[NT], en[NT];
    int b = blockIdx.x, tid = threadIdx.x;
    for (int i = tid; i < NT * NT; i += 32) tr[i] = ctrans[i];
    if (tid < NT){ st[tid] = cstart[tid]; en[tid] = cend[tid]; }
    const float* lg = logits + (size_t)b * SEQ * NT;
    const int* lab = labels + b * SEQ;
    if (tid < NT) score[tid] = st[tid] + lg[tid];
    __syncwarp();
    for (int s = 1; s < SEQ; s++){
        float nxt = 0.f;
        if (tid < NT){
            float m = -INFINITY;
            #pragma unroll
            for (int i = 0; i < NT; i++) m = fmaxf(m, score[i] + tr[i * NT + tid]);
            float sum = 0.f;
            #pragma unroll
            for (int i = 0; i < NT; i++) sum += expf(score[i] + tr[i * NT + tid] - m);
            nxt = m + logf(sum) + lg[s * NT + tid];
        }
        bool msk = (lab[s] != -100);
        __syncwarp();
        if (tid < NT && msk) score[tid] = nxt;
        __syncwarp();
    }
    if (tid == 0){
        float m = -INFINITY;
        for (int t = 0; t < NT; t++) m = fmaxf(m, score[t] + en[t]);
        float sum = 0.f;
        for (int t = 0; t < NT; t++) sum += expf(score[t] + en[t] - m);
        float denom = m + logf(sum);
        int l0 = lab[0];
        int tag_prev = (l0 == -100) ? 0 : l0;
        float num = st[tag_prev] + lg[tag_prev];
        int cnt = 1;
        for (int s = 1; s < SEQ; s++){
            int ls = lab[s];
            bool msk = (ls != -100);
            int tg = msk ? ls : 0;
            if (msk){
                num += tr[tag_prev * NT + tg] + lg[s * NT + tg];
                cnt++;
            }
            tag_prev = tg;
        }
        int seq_end = cnt - 1;
        int le = lab[seq_end];
        int last_tag = (le == -100) ? 0 : le;
        num += en[last_tag];
        res[b] = num - denom;
    }
}

// ---------------- finalize ----------------
__global__ void finalize_kernel(const float* __restrict__ res,
                                const float* __restrict__ logits,
                                float* __restrict__ out, int nlog){
    int idx = blockIdx.x * blockDim.x + threadIdx.x;
    if (idx == 0){
        float s = 0.f;
        for (int b = 0; b < BSZ; b++) s += res[b];
        out[0] = -s / BSZ;
    }
    if (idx < nlog) out[1 + idx] = logits[idx];
}

// ---------------- launch ----------------
extern "C" void kernel_launch(void* const* d_in, const int* in_sizes, int n_in,
                              void* d_out, int out_size){
    const int*   input_ids = (const int*)  d_in[0];
    const int*   amask     = (const int*)  d_in[1];
    const int*   labels    = (const int*)  d_in[2];
    const float* word_emb  = (const float*)d_in[3];
    const float* pos_emb   = (const float*)d_in[4];
    const float* emb_ln_s  = (const float*)d_in[5];
    const float* emb_ln_b  = (const float*)d_in[6];
    const float* Wqkv      = (const float*)d_in[7];
    const float* bqkv      = (const float*)d_in[8];
    const float* Wo        = (const float*)d_in[9];
    const float* bo        = (const float*)d_in[10];
    const float* ln1_s     = (const float*)d_in[11];
    const float* ln1_b     = (const float*)d_in[12];
    const float* Wff1      = (const float*)d_in[13];
    const float* bff1      = (const float*)d_in[14];
    const float* Wff2      = (const float*)d_in[15];
    const float* bff2      = (const float*)d_in[16];
    const float* ln2_s     = (const float*)d_in[17];
    const float* ln2_b     = (const float*)d_in[18];
    const float* Wcls      = (const float*)d_in[19];
    const float* bcls      = (const float*)d_in[20];
    const float* crf_start = (const float*)d_in[21];
    const float* crf_end   = (const float*)d_in[22];
    const float* crf_trans = (const float*)d_in[23];

    float *x, *h1, *tmp, *qkv, *attn, *ffn, *logits, *res;
    cudaGetSymbolAddress((void**)&x,      g_x);
    cudaGetSymbolAddress((void**)&h1,     g_h1);
    cudaGetSymbolAddress((void**)&tmp,    g_tmp);
    cudaGetSymbolAddress((void**)&qkv,    g_qkv);
    cudaGetSymbolAddress((void**)&attn,   g_attn);
    cudaGetSymbolAddress((void**)&ffn,    g_ffn);
    cudaGetSymbolAddress((void**)&logits, g_logits);
    cudaGetSymbolAddress((void**)&res,    g_res);

    static int smem_set = 0;
    if (!smem_set){
        cudaFuncSetAttribute(attn2_kernel,
                             cudaFuncAttributeMaxDynamicSharedMemorySize, ATT_SMEM);
        smem_set = 1;
    }

    embed_kernel<<<TOK, 256>>>(input_ids, word_emb, pos_emb, emb_ln_s, emb_ln_b, x);

    for (int l = 0; l < NLAYERS; l++){
        const float* wqkv = Wqkv + (size_t)l * HID * 3 * HID;
        const float* bq   = bqkv + (size_t)l * 3 * HID;
        const float* wo   = Wo   + (size_t)l * HID * HID;
        const float* bo_  = bo   + (size_t)l * HID;
        const float* s1   = ln1_s + (size_t)l * HID;
        const float* b1   = ln1_b + (size_t)l * HID;
        const float* w1   = Wff1 + (size_t)l * HID * FFN;
        const float* bf1  = bff1 + (size_t)l * FFN;
        const float* w2   = Wff2 + (size_t)l * FFN * HID;
        const float* bf2  = bff2 + (size_t)l * HID;
        const float* s2   = ln2_s + (size_t)l * HID;
        const float* b2   = ln2_b + (size_t)l * HID;

        gemm_tc<<<dim3(3 * HID / 128, TOK / 128), 256>>>(x, wqkv, bq, qkv, TOK, 3 * HID, HID, 0);
        attn2_kernel<<<dim3(SEQ / 128, NH, BSZ), 256, ATT_SMEM>>>(qkv, amask, attn);
        gemm_tc<<<dim3(HID / 128, TOK / 128), 256>>>(attn, wo, bo_, tmp, TOK, HID, HID, 0);
        ln_residual_kernel<<<TOK, 256>>>(x, tmp, s1, b1, h1);
        gemm_tc<<<dim3(FFN / 128, TOK / 128), 256>>>(h1, w1, bf1, ffn, TOK, FFN, HID, 1);
        gemm_tc<<<dim3(HID / 128, TOK / 128), 256>>>(ffn, w2, bf2, tmp, TOK, HID, FFN, 0);
        ln_residual_kernel<<<TOK, 256>>>(h1, tmp, s2, b2, x);
    }

    cls_kernel<<<TOK, 288>>>(x, Wcls, bcls, logits);
    crf_kernel<<<BSZ, 32>>>(logits, labels, crf_start, crf_end, crf_trans, res);
    int nlog = TOK * NT;
    finalize_kernel<<<(nlog + 256) / 256, 256>>>(res, logits, (float*)d_out, nlog);
}

// round 3
// speedup vs baseline: 6.2161x; 1.2694x over previous
#include <cuda_runtime.h>
#include <cuda_bf16.h>
#include <math.h>
#include <stdint.h>

#define BSZ 16
#define SEQ 256
#define HID 768
#define TOK (BSZ*SEQ)      // 4096
#define FFN 3072
#define NH 12
#define HD 64
#define NT 9
#define NLAYERS 6

// ---------------- scratch (static device globals; no allocations) ----------------
__device__ float g_x[TOK*HID];
__device__ float g_h1[TOK*HID];
__device__ float g_tmp[TOK*HID];
__device__ float g_qkv[TOK*3*HID];
__device__ float g_attn[TOK*HID];
__device__ float g_ffn[(size_t)TOK*FFN];
__device__ float g_logits[TOK*NT];
__device__ float g_res[BSZ];

// ---------------- reductions ----------------
__device__ __forceinline__ float warpReduceSum(float v){
    #pragma unroll
    for (int o = 16; o; o >>= 1) v += __shfl_xor_sync(0xffffffffu, v, o);
    return v;
}
__device__ __forceinline__ float warpReduceMax(float v){
    #pragma unroll
    for (int o = 16; o; o >>= 1) v = fmaxf(v, __shfl_xor_sync(0xffffffffu, v, o));
    return v;
}
__device__ float blockReduceSum(float v, float* sh){
    __syncthreads();
    int lane = threadIdx.x & 31, wid = threadIdx.x >> 5;
    v = warpReduceSum(v);
    if (lane == 0) sh[wid] = v;
    __syncthreads();
    int nw = blockDim.x >> 5;
    v = (threadIdx.x < nw) ? sh[threadIdx.x] : 0.0f;
    if (wid == 0) v = warpReduceSum(v);
    if (threadIdx.x == 0) sh[0] = v;
    __syncthreads();
    return sh[0];
}

__device__ __forceinline__ float gelu_tanh(float x){
    float x3 = x * x * x;
    return 0.5f * x * (1.0f + tanhf(0.7978845608028654f * (x + 0.044715f * x3)));
}

// ---------------- tf32 / async helpers ----------------
__device__ __forceinline__ uint32_t f2tf32(float f){
    uint32_t r; asm("cvt.rna.tf32.f32 %0, %1;" : "=r"(r) : "f"(f)); return r;
}
__device__ __forceinline__ void mma_tf32(float* c, const uint32_t* a, const uint32_t* b){
    asm volatile(
        "mma.sync.aligned.m16n8k8.row.col.f32.tf32.tf32.f32 "
        "{%0,%1,%2,%3},{%4,%5,%6,%7},{%8,%9},{%0,%1,%2,%3};"
        : "+f"(c[0]), "+f"(c[1]), "+f"(c[2]), "+f"(c[3])
        : "r"(a[0]), "r"(a[1]), "r"(a[2]), "r"(a[3]), "r"(b[0]), "r"(b[1]));
}
__device__ __forceinline__ void cpasync16(float* smem, const float* g){
    uint32_t s = (uint32_t)__cvta_generic_to_shared(smem);
    asm volatile("cp.async.cg.shared.global [%0], [%1], 16;" :: "r"(s), "l"(g));
}
#define CP_COMMIT() asm volatile("cp.async.commit_group;")
#define CP_WAIT(n)  asm volatile("cp.async.wait_group %0;" :: "n"(n))

// ---------------- embedding + LN ----------------
__global__ void embed_kernel(const int* __restrict__ ids,
                             const float* __restrict__ we,
                             const float* __restrict__ pe,
                             const float* __restrict__ gamma,
                             const float* __restrict__ beta,
                             float* __restrict__ out){
    __shared__ float sh[32];
    int tok = blockIdx.x;
    int sI = tok % SEQ;
    int id = ids[tok];
    const float* wrow = we + (size_t)id * HID;
    const float* prow = pe + (size_t)sI * HID;
    float vals[3]; float lsum = 0.f;
    #pragma unroll
    for (int i = 0; i < 3; i++){
        int d = threadIdx.x + i * 256;
        float v = wrow[d] + prow[d];
        vals[i] = v; lsum += v;
    }
    float mean = blockReduceSum(lsum, sh) * (1.0f / HID);
    float lss = 0.f;
    #pragma unroll
    for (int i = 0; i < 3; i++){ float d0 = vals[i] - mean; lss += d0 * d0; }
    float var = blockReduceSum(lss, sh) * (1.0f / HID);
    float rstd = rsqrtf(var + 1e-12f);
    float* orow = out + (size_t)tok * HID;
    #pragma unroll
    for (int i = 0; i < 3; i++){
        int d = threadIdx.x + i * 256;
        orow[d] = (vals[i] - mean) * rstd * gamma[d] + beta[d];
    }
}

// ---------------- residual + LN ----------------
__global__ void ln_residual_kernel(const float* __restrict__ a,
                                   const float* __restrict__ c,
                                   const float* __restrict__ gamma,
                                   const float* __restrict__ beta,
                                   float* __restrict__ out){
    __shared__ float sh[32];
    int tok = blockIdx.x;
    const float* ar = a + (size_t)tok * HID;
    const float* cr = c + (size_t)tok * HID;
    float vals[3]; float lsum = 0.f;
    #pragma unroll
    for (int i = 0; i < 3; i++){
        int d = threadIdx.x + i * 256;
        float v = ar[d] + cr[d];
        vals[i] = v; lsum += v;
    }
    float mean = blockReduceSum(lsum, sh) * (1.0f / HID);
    float lss = 0.f;
    #pragma unroll
    for (int i = 0; i < 3; i++){ float d0 = vals[i] - mean; lss += d0 * d0; }
    float var = blockReduceSum(lss, sh) * (1.0f / HID);
    float rstd = rsqrtf(var + 1e-12f);
    float* orow = out + (size_t)tok * HID;
    #pragma unroll
    for (int i = 0; i < 3; i++){
        int d = threadIdx.x + i * 256;
        orow[d] = (vals[i] - mean) * rstd * gamma[d] + beta[d];
    }
}

// ---------------- tf32 TC GEMM v2: cp.async double-buffered -------------------
// C[M,N] = A[M,K] @ W[K,N] + bias (opt gelu)
// block 128x128, BK=32, 256 thr = 8 warps (4x2), warp tile 32x64, 2 smem stages.
// As: [stage][128][36]  ([m][k], stride 36 -> conflict-free frag loads)
// Bs: [stage][32][136]  ([k][n], stride 136 -> conflict-free frag loads)
#define AS_STRIDE 36
#define BS_STRIDE 136
#define GEMM_SMEM ((2*128*AS_STRIDE + 2*32*BS_STRIDE) * 4)

__global__ void __launch_bounds__(256, 2)
gemm_tc(const float* __restrict__ A,
        const float* __restrict__ W,
        const float* __restrict__ bias,
        float* __restrict__ C,
        int M, int N, int K, int act){
    extern __shared__ float sm[];
    float* As = sm;                       // 2*128*36
    float* Bs = sm + 2 * 128 * AS_STRIDE; // 2*32*136

    int tid = threadIdx.x;
    int wid = tid >> 5, lane = tid & 31;
    int warpRow = wid >> 1, warpCol = wid & 1;
    int gid = lane >> 2, tig = lane & 3;
    int rowBase = blockIdx.y * 128, colBase = blockIdx.x * 128;

    // A copy mapping: thread t -> row t>>1, 4 quads at col (t&1)*16 + j*4
    int a_r = tid >> 1;
    int a_c = (tid & 1) * 16;
    const float* a_g = A + (size_t)(rowBase + a_r) * K + a_c;
    // B copy mapping: thread t -> row t>>3, 4 quads at col (t&7)*4 + j*32
    int b_r = tid >> 3;
    int b_c = (tid & 7) * 4;

    float acc[2][8][4];
    #pragma unroll
    for (int mi = 0; mi < 2; mi++)
        #pragma unroll
        for (int ni = 0; ni < 8; ni++)
            #pragma unroll
            for (int j = 0; j < 4; j++) acc[mi][ni][j] = 0.f;

    int ntile = K >> 5;

    // prologue: load tile 0 into stage 0
    {
        float* as = As;
        float* bs = Bs;
        #pragma unroll
        for (int j = 0; j < 4; j++)
            cpasync16(as + a_r * AS_STRIDE + a_c + j * 4, a_g + j * 4);
        const float* w_g = W + (size_t)b_r * N + colBase + b_c;
        #pragma unroll
        for (int j = 0; j < 4; j++)
            cpasync16(bs + b_r * BS_STRIDE + b_c + j * 32, w_g + j * 32);
        CP_COMMIT();
    }

    for (int t = 0; t < ntile; t++){
        if (t + 1 < ntile){
            int st = (t + 1) & 1;
            float* as = As + st * 128 * AS_STRIDE;
            float* bs = Bs + st * 32 * BS_STRIDE;
            int k0 = (t + 1) << 5;
            #pragma unroll
            for (int j = 0; j < 4; j++)
                cpasync16(as + a_r * AS_STRIDE + a_c + j * 4, a_g + k0 + j * 4);
            const float* w_g = W + (size_t)(k0 + b_r) * N + colBase + b_c;
            #pragma unroll
            for (int j = 0; j < 4; j++)
                cpasync16(bs + b_r * BS_STRIDE + b_c + j * 32, w_g + j * 32);
            CP_COMMIT();
            CP_WAIT(1);
        } else {
            CP_WAIT(0);
        }
        __syncthreads();

        int st = t & 1;
        const float* as = As + st * 128 * AS_STRIDE;
        const float* bs = Bs + st * 32 * BS_STRIDE;
        #pragma unroll
        for (int ks = 0; ks < 4; ks++){
            int kb = ks * 8;
            uint32_t af[2][4], bf[8][2];
            #pragma unroll
            for (int mi = 0; mi < 2; mi++){
                int m0 = warpRow * 32 + mi * 16;
                const float* ar0 = as + (m0 + gid) * AS_STRIDE + kb + tig;
                const float* ar1 = as + (m0 + gid + 8) * AS_STRIDE + kb + tig;
                af[mi][0] = f2tf32(ar0[0]);
                af[mi][1] = f2tf32(ar1[0]);
                af[mi][2] = f2tf32(ar0[4]);
                af[mi][3] = f2tf32(ar1[4]);
            }
            #pragma unroll
            for (int ni = 0; ni < 8; ni++){
                int n0 = warpCol * 64 + ni * 8;
                bf[ni][0] = f2tf32(bs[(kb + tig) * BS_STRIDE + n0 + gid]);
                bf[ni][1] = f2tf32(bs[(kb + tig + 4) * BS_STRIDE + n0 + gid]);
            }
            #pragma unroll
            for (int mi = 0; mi < 2; mi++)
                #pragma unroll
                for (int ni = 0; ni < 8; ni++)
                    mma_tf32(acc[mi][ni], af[mi], bf[ni]);
        }
        __syncthreads();
    }

    // epilogue
    #pragma unroll
    for (int mi = 0; mi < 2; mi++){
        int r0 = rowBase + warpRow * 32 + mi * 16 + gid;
        #pragma unroll
        for (int ni = 0; ni < 8; ni++){
            int cc = colBase + warpCol * 64 + ni * 8 + tig * 2;
            float b0 = bias[cc], b1 = bias[cc + 1];
            float v0 = acc[mi][ni][0] + b0, v1 = acc[mi][ni][1] + b1;
            float v2 = acc[mi][ni][2] + b0, v3 = acc[mi][ni][3] + b1;
            if (act == 1){
                v0 = gelu_tanh(v0); v1 = gelu_tanh(v1);
                v2 = gelu_tanh(v2); v3 = gelu_tanh(v3);
            }
            *(float2*)&C[(size_t)r0 * N + cc] = make_float2(v0, v1);
            *(float2*)&C[(size_t)(r0 + 8) * N + cc] = make_float2(v2, v3);
        }
    }
}

// ---------------- attention: flash-style (unchanged from R2) ------------------
#define ATT_SMEM ((128*64 + 64*64 + 64*64 + 8*4*64 + 256) * 4)
__global__ void attn2_kernel(const float* __restrict__ qkv,
                             const int* __restrict__ amask,
                             float* __restrict__ out){
    extern __shared__ float sm[];
    float* Qs = sm;
    float* Kt = Qs + 128 * 64;
    float* Vs = Kt + 64 * 64;
    float* ps = Vs + 64 * 64;
    float* bs = ps + 8 * 4 * 64;
    int tid = threadIdx.x, w = tid >> 5, lane = tid & 31;
    int qb = blockIdx.x * 128, h = blockIdx.y, b = blockIdx.z;
    const size_t rs = 3 * HID;
    const float* base = qkv + (size_t)b * SEQ * rs;

    bs[tid] = (1.0f - (float)amask[b * SEQ + tid]) * -1e9f;

    #pragma unroll
    for (int pass = 0; pass < 2; pass++){
        int q = (tid >> 2) + pass * 64;
        int d0 = (tid & 3) * 16;
        const float* src = base + (size_t)(qb + q) * rs + h * HD + d0;
        float* dst = Qs + q * 64 + d0;
        #pragma unroll
        for (int j = 0; j < 4; j++)
            *(float4*)(dst + j * 4) = *(const float4*)(src + j * 4);
    }

    float mJ[16], sJ[16], a0[16], a1[16];
    #pragma unroll
    for (int i = 0; i < 16; i++){ mJ[i] = -INFINITY; sJ[i] = 0.f; a0[i] = 0.f; a1[i] = 0.f; }

    for (int c = 0; c < 4; c++){
        __syncthreads();
        {
            int k = tid >> 2;
            int d0 = (tid & 3) * 16;
            const float* ksrc = base + (size_t)(c * 64 + k) * rs + HID + h * HD + d0;
            const float* vsrc = base + (size_t)(c * 64 + k) * rs + 2 * HID + h * HD + d0;
            #pragma unroll
            for (int j = 0; j < 4; j++){
                float4 kv = *(const float4*)(ksrc + j * 4);
                Kt[(d0 + j * 4 + 0) * 64 + k] = kv.x;
                Kt[(d0 + j * 4 + 1) * 64 + k] = kv.y;
                Kt[(d0 + j * 4 + 2) * 64 + k] = kv.z;
                Kt[(d0 + j * 4 + 3) * 64 + k] = kv.w;
                *(float4*)(Vs + k * 64 + d0 + j * 4) = *(const float4*)(vsrc + j * 4);
            }
        }
        __syncthreads();

        #pragma unroll 1
        for (int ib = 0; ib < 4; ib++){
            int i0 = ib * 4;
            float sc[4][2];
            #pragma unroll
            for (int j = 0; j < 4; j++){ sc[j][0] = 0.f; sc[j][1] = 0.f; }
            const float* q0 = Qs + (w * 16 + i0) * 64;
            #pragma unroll 8
            for (int d = 0; d < 64; d++){
                float kt0 = Kt[d * 64 + lane];
                float kt1 = Kt[d * 64 + lane + 32];
                #pragma unroll
                for (int j = 0; j < 4; j++){
                    float qv = q0[j * 64 + d];
                    sc[j][0] = fmaf(qv, kt0, sc[j][0]);
                    sc[j][1] = fmaf(qv, kt1, sc[j][1]);
                }
            }
            float bm0 = bs[c * 64 + lane], bm1 = bs[c * 64 + lane + 32];
            #pragma unroll
            for (int j = 0; j < 4; j++){
                int i = i0 + j;
                float s0 = sc[j][0] * 0.125f + bm0;
                float s1 = sc[j][1] * 0.125f + bm1;
                float mx = warpReduceMax(fmaxf(s0, s1));
                float nm = fmaxf(mJ[i], mx);
                float e0 = __expf(s0 - nm), e1 = __expf(s1 - nm);
                float sumc = warpReduceSum(e0 + e1);
                float corr = __expf(mJ[i] - nm);
                sJ[i] = sJ[i] * corr + sumc;
                mJ[i] = nm;
                a0[i] *= corr; a1[i] *= corr;
                ps[(w * 4 + j) * 64 + lane] = e0;
                ps[(w * 4 + j) * 64 + lane + 32] = e1;
            }
            __syncwarp();
            float x0[4], x1[4];
            #pragma unroll
            for (int j = 0; j < 4; j++){ x0[j] = a0[i0 + j]; x1[j] = a1[i0 + j]; }
            #pragma unroll 4
            for (int k = 0; k < 64; k++){
                float v0 = Vs[k * 64 + lane];
                float v1 = Vs[k * 64 + lane + 32];
                #pragma unroll
                for (int j = 0; j < 4; j++){
                    float p = ps[(w * 4 + j) * 64 + k];
                    x0[j] = fmaf(p, v0, x0[j]);
                    x1[j] = fmaf(p, v1, x1[j]);
                }
            }
            #pragma unroll
            for (int j = 0; j < 4; j++){ a0[i0 + j] = x0[j]; a1[i0 + j] = x1[j]; }
            __syncwarp();
        }
    }
    #pragma unroll
    for (int i = 0; i < 16; i++){
        int q = qb + w * 16 + i;
        float inv = 1.0f / sJ[i];
        size_t o = (size_t)(b * SEQ + q) * HID + h * HD;
        out[o + lane]      = a0[i] * inv;
        out[o + lane + 32] = a1[i] * inv;
    }
}

// ---------------- classifier ----------------
__global__ void cls_kernel(const float* __restrict__ x,
                           const float* __restrict__ W,
                           const float* __restrict__ bias,
                           float* __restrict__ logits){
    __shared__ float xs[HID];
    int tok = blockIdx.x;
    for (int d = threadIdx.x; d < HID; d += blockDim.x)
        xs[d] = x[(size_t)tok * HID + d];
    __syncthreads();
    int w = threadIdx.x >> 5, lane = threadIdx.x & 31;
    float acc = 0.f;
    for (int d = lane; d < HID; d += 32)
        acc = fmaf(xs[d], W[d * NT + w], acc);
    acc = warpReduceSum(acc);
    if (lane == 0) logits[tok * NT + w] = acc + bias[w];
}

// ---------------- CRF ----------------
__global__ void crf_kernel(const float* __restrict__ logits,
                           const int* __restrict__ labels,
                           const float* __restrict__ cstart,
                           const float* __restrict__ cend,
                           const float* __restrict__ ctrans,
                           float* __restrict__ res){
    __shared__ float score[NT];
    __shared__ float tr[NT * NT];
    __shared__ float st[NT], en[NT];
    int b = blockIdx.x, tid = threadIdx.x;
    for (int i = tid; i < NT * NT; i += 32) tr[i] = ctrans[i];
    if (tid < NT){ st[tid] = cstart[tid]; en[tid] = cend[tid]; }
    const float* lg = logits + (size_t)b * SEQ * NT;
    const int* lab = labels + b * SEQ;
    if (tid < NT) score[tid] = st[tid] + lg[tid];
    __syncwarp();
    for (int s = 1; s < SEQ; s++){
        float nxt = 0.f;
        if (tid < NT){
            float m = -INFINITY;
            #pragma unroll
            for (int i = 0; i < NT; i++) m = fmaxf(m, score[i] + tr[i * NT + tid]);
            float sum = 0.f;
            #pragma unroll
            for (int i = 0; i < NT; i++) sum += expf(score[i] + tr[i * NT + tid] - m);
            nxt = m + logf(sum) + lg[s * NT + tid];
        }
        bool msk = (lab[s] != -100);
        __syncwarp();
        if (tid < NT && msk) score[tid] = nxt;
        __syncwarp();
    }
    if (tid == 0){
        float m = -INFINITY;
        for (int t = 0; t < NT; t++) m = fmaxf(m, score[t] + en[t]);
        float sum = 0.f;
        for (int t = 0; t < NT; t++) sum += expf(score[t] + en[t] - m);
        float denom = m + logf(sum);
        int l0 = lab[0];
        int tag_prev = (l0 == -100) ? 0 : l0;
        float num = st[tag_prev] + lg[tag_prev];
        int cnt = 1;
        for (int s = 1; s < SEQ; s++){
            int ls = lab[s];
            bool msk = (ls != -100);
            int tg = msk ? ls : 0;
            if (msk){
                num += tr[tag_prev * NT + tg] + lg[s * NT + tg];
                cnt++;
            }
            tag_prev = tg;
        }
        int seq_end = cnt - 1;
        int le = lab[seq_end];
        int last_tag = (le == -100) ? 0 : le;
        num += en[last_tag];
        res[b] = num - denom;
    }
}

// ---------------- finalize ----------------
__global__ void finalize_kernel(const float* __restrict__ res,
                                const float* __restrict__ logits,
                                float* __restrict__ out, int nlog){
    int idx = blockIdx.x * blockDim.x + threadIdx.x;
    if (idx == 0){
        float s = 0.f;
        for (int b = 0; b < BSZ; b++) s += res[b];
        out[0] = -s / BSZ;
    }
    if (idx < nlog) out[1 + idx] = logits[idx];
}

// ---------------- launch ----------------
extern "C" void kernel_launch(void* const* d_in, const int* in_sizes, int n_in,
                              void* d_out, int out_size){
    const int*   input_ids = (const int*)  d_in[0];
    const int*   amask     = (const int*)  d_in[1];
    const int*   labels    = (const int*)  d_in[2];
    const float* word_emb  = (const float*)d_in[3];
    const float* pos_emb   = (const float*)d_in[4];
    const float* emb_ln_s  = (const float*)d_in[5];
    const float* emb_ln_b  = (const float*)d_in[6];
    const float* Wqkv      = (const float*)d_in[7];
    const float* bqkv      = (const float*)d_in[8];
    const float* Wo        = (const float*)d_in[9];
    const float* bo        = (const float*)d_in[10];
    const float* ln1_s     = (const float*)d_in[11];
    const float* ln1_b     = (const float*)d_in[12];
    const float* Wff1      = (const float*)d_in[13];
    const float* bff1      = (const float*)d_in[14];
    const float* Wff2      = (const float*)d_in[15];
    const float* bff2      = (const float*)d_in[16];
    const float* ln2_s     = (const float*)d_in[17];
    const float* ln2_b     = (const float*)d_in[18];
    const float* Wcls      = (const float*)d_in[19];
    const float* bcls      = (const float*)d_in[20];
    const float* crf_start = (const float*)d_in[21];
    const float* crf_end   = (const float*)d_in[22];
    const float* crf_trans = (const float*)d_in[23];

    float *x, *h1, *tmp, *qkv, *attn, *ffn, *logits, *res;
    cudaGetSymbolAddress((void**)&x,      g_x);
    cudaGetSymbolAddress((void**)&h1,     g_h1);
    cudaGetSymbolAddress((void**)&tmp,    g_tmp);
    cudaGetSymbolAddress((void**)&qkv,    g_qkv);
    cudaGetSymbolAddress((void**)&attn,   g_attn);
    cudaGetSymbolAddress((void**)&ffn,    g_ffn);
    cudaGetSymbolAddress((void**)&logits, g_logits);
    cudaGetSymbolAddress((void**)&res,    g_res);

    static int smem_set = 0;
    if (!smem_set){
        cudaFuncSetAttribute(attn2_kernel,
                             cudaFuncAttributeMaxDynamicSharedMemorySize, ATT_SMEM);
        cudaFuncSetAttribute(gemm_tc,
                             cudaFuncAttributeMaxDynamicSharedMemorySize, GEMM_SMEM);
        smem_set = 1;
    }

    embed_kernel<<<TOK, 256>>>(input_ids, word_emb, pos_emb, emb_ln_s, emb_ln_b, x);

    for (int l = 0; l < NLAYERS; l++){
        const float* wqkv = Wqkv + (size_t)l * HID * 3 * HID;
        const float* bq   = bqkv + (size_t)l * 3 * HID;
        const float* wo   = Wo   + (size_t)l * HID * HID;
        const float* bo_  = bo   + (size_t)l * HID;
        const float* s1   = ln1_s + (size_t)l * HID;
        const float* b1   = ln1_b + (size_t)l * HID;
        const float* w1   = Wff1 + (size_t)l * HID * FFN;
        const float* bf1  = bff1 + (size_t)l * FFN;
        const float* w2   = Wff2 + (size_t)l * FFN * HID;
        const float* bf2  = bff2 + (size_t)l * HID;
        const float* s2   = ln2_s + (size_t)l * HID;
        const float* b2   = ln2_b + (size_t)l * HID;

        gemm_tc<<<dim3(3 * HID / 128, TOK / 128), 256, GEMM_SMEM>>>(x, wqkv, bq, qkv, TOK, 3 * HID, HID, 0);
        attn2_kernel<<<dim3(SEQ / 128, NH, BSZ), 256, ATT_SMEM>>>(qkv, amask, attn);
        gemm_tc<<<dim3(HID / 128, TOK / 128), 256, GEMM_SMEM>>>(attn, wo, bo_, tmp, TOK, HID, HID, 0);
        ln_residual_kernel<<<TOK, 256>>>(x, tmp, s1, b1, h1);
        gemm_tc<<<dim3(FFN / 128, TOK / 128), 256, GEMM_SMEM>>>(h1, w1, bf1, ffn, TOK, FFN, HID, 1);
        gemm_tc<<<dim3(HID / 128, TOK / 128), 256, GEMM_SMEM>>>(ffn, w2, bf2, tmp, TOK, HID, FFN, 0);
        ln_residual_kernel<<<TOK, 256>>>(h1, tmp, s2, b2, x);
    }

    cls_kernel<<<TOK, 288>>>(x, Wcls, bcls, logits);
    crf_kernel<<<BSZ, 32>>>(logits, labels, crf_start, crf_end, crf_trans, res);
    int nlog = TOK * NT;
    finalize_kernel<<<(nlog + 256) / 256, 256>>>(res, logits, (float*)d_out, nlog);
}

// round 5
// speedup vs baseline: 7.1248x; 1.1462x over previous
#include <cuda_runtime.h>
#include <cuda_bf16.h>
#include <math.h>
#include <stdint.h>

#define BSZ 16
#define SEQ 256
#define HID 768
#define TOK (BSZ*SEQ)      // 4096
#define FFN 3072
#define NH 12
#define HD 64
#define NT 9
#define NLAYERS 6

// ---------------- scratch (static device globals; no allocations) ----------------
__device__ float g_x[TOK*HID];
__device__ float g_h1[TOK*HID];
__device__ float g_tmp[TOK*HID];
__device__ float g_qkv[TOK*3*HID];
__device__ float g_attn[TOK*HID];
__device__ float g_ffn[(size_t)TOK*FFN];
__device__ float g_logits[TOK*NT];
__device__ float g_res[BSZ];

// ---------------- reductions ----------------
__device__ __forceinline__ float warpReduceSum(float v){
    #pragma unroll
    for (int o = 16; o; o >>= 1) v += __shfl_xor_sync(0xffffffffu, v, o);
    return v;
}
__device__ float blockReduceSum(float v, float* sh){
    __syncthreads();
    int lane = threadIdx.x & 31, wid = threadIdx.x >> 5;
    v = warpReduceSum(v);
    if (lane == 0) sh[wid] = v;
    __syncthreads();
    int nw = blockDim.x >> 5;
    v = (threadIdx.x < nw) ? sh[threadIdx.x] : 0.0f;
    if (wid == 0) v = warpReduceSum(v);
    if (threadIdx.x == 0) sh[0] = v;
    __syncthreads();
    return sh[0];
}

__device__ __forceinline__ float gelu_tanh(float x){
    float x3 = x * x * x;
    return 0.5f * x * (1.0f + tanhf(0.7978845608028654f * (x + 0.044715f * x3)));
}

// ---------------- tf32 / async helpers ----------------
__device__ __forceinline__ uint32_t f2tf32(float f){
    uint32_t r; asm("cvt.rna.tf32.f32 %0, %1;" : "=r"(r) : "f"(f)); return r;
}
__device__ __forceinline__ void mma_tf32(float* c, const uint32_t* a, const uint32_t* b){
    asm volatile(
        "mma.sync.aligned.m16n8k8.row.col.f32.tf32.tf32.f32 "
        "{%0,%1,%2,%3},{%4,%5,%6,%7},{%8,%9},{%0,%1,%2,%3};"
        : "+f"(c[0]), "+f"(c[1]), "+f"(c[2]), "+f"(c[3])
        : "r"(a[0]), "r"(a[1]), "r"(a[2]), "r"(a[3]), "r"(b[0]), "r"(b[1]));
}
__device__ __forceinline__ void cpasync16(float* smem, const float* g){
    uint32_t s = (uint32_t)__cvta_generic_to_shared(smem);
    asm volatile("cp.async.cg.shared.global [%0], [%1], 16;" :: "r"(s), "l"(g));
}
#define CP_COMMIT() asm volatile("cp.async.commit_group;")
#define CP_WAIT(n)  asm volatile("cp.async.wait_group %0;" :: "n"(n))

// ---------------- embedding + LN ----------------
__global__ void embed_kernel(const int* __restrict__ ids,
                             const float* __restrict__ we,
                             const float* __restrict__ pe,
                             const float* __restrict__ gamma,
                             const float* __restrict__ beta,
                             float* __restrict__ out){
    __shared__ float sh[32];
    int tok = blockIdx.x;
    int sI = tok % SEQ;
    int id = ids[tok];
    const float* wrow = we + (size_t)id * HID;
    const float* prow = pe + (size_t)sI * HID;
    float vals[3]; float lsum = 0.f;
    #pragma unroll
    for (int i = 0; i < 3; i++){
        int d = threadIdx.x + i * 256;
        float v = wrow[d] + prow[d];
        vals[i] = v; lsum += v;
    }
    float mean = blockReduceSum(lsum, sh) * (1.0f / HID);
    float lss = 0.f;
    #pragma unroll
    for (int i = 0; i < 3; i++){ float d0 = vals[i] - mean; lss += d0 * d0; }
    float var = blockReduceSum(lss, sh) * (1.0f / HID);
    float rstd = rsqrtf(var + 1e-12f);
    float* orow = out + (size_t)tok * HID;
    #pragma unroll
    for (int i = 0; i < 3; i++){
        int d = threadIdx.x + i * 256;
        orow[d] = (vals[i] - mean) * rstd * gamma[d] + beta[d];
    }
}

// ---------------- residual + LN ----------------
__global__ void ln_residual_kernel(const float* __restrict__ a,
                                   const float* __restrict__ c,
                                   const float* __restrict__ gamma,
                                   const float* __restrict__ beta,
                                   float* __restrict__ out){
    __shared__ float sh[32];
    int tok = blockIdx.x;
    const float* ar = a + (size_t)tok * HID;
    const float* cr = c + (size_t)tok * HID;
    float vals[3]; float lsum = 0.f;
    #pragma unroll
    for (int i = 0; i < 3; i++){
        int d = threadIdx.x + i * 256;
        float v = ar[d] + cr[d];
        vals[i] = v; lsum += v;
    }
    float mean = blockReduceSum(lsum, sh) * (1.0f / HID);
    float lss = 0.f;
    #pragma unroll
    for (int i = 0; i < 3; i++){ float d0 = vals[i] - mean; lss += d0 * d0; }
    float var = blockReduceSum(lss, sh) * (1.0f / HID);
    float rstd = rsqrtf(var + 1e-12f);
    float* orow = out + (size_t)tok * HID;
    #pragma unroll
    for (int i = 0; i < 3; i++){
        int d = threadIdx.x + i * 256;
        orow[d] = (vals[i] - mean) * rstd * gamma[d] + beta[d];
    }
}

// ---------------- tf32 TC GEMM: cp.async double-buffered, RNA rounding -------
#define AS_STRIDE 36
#define BS_STRIDE 136
#define GEMM_SMEM ((2*128*AS_STRIDE + 2*32*BS_STRIDE) * 4)

__global__ void __launch_bounds__(256, 2)
gemm_tc(const float* __restrict__ A,
        const float* __restrict__ W,
        const float* __restrict__ bias,
        float* __restrict__ C,
        int M, int N, int K, int act){
    extern __shared__ float sm[];
    float* As = sm;
    float* Bs = sm + 2 * 128 * AS_STRIDE;

    int tid = threadIdx.x;
    int wid = tid >> 5, lane = tid & 31;
    int warpRow = wid >> 1, warpCol = wid & 1;
    int gid = lane >> 2, tig = lane & 3;
    int rowBase = blockIdx.y * 128, colBase = blockIdx.x * 128;

    int a_r = tid >> 1;
    int a_c = (tid & 1) * 16;
    const float* a_g = A + (size_t)(rowBase + a_r) * K + a_c;
    int b_r = tid >> 3;
    int b_c = (tid & 7) * 4;

    float acc[2][8][4];
    #pragma unroll
    for (int mi = 0; mi < 2; mi++)
        #pragma unroll
        for (int ni = 0; ni < 8; ni++)
            #pragma unroll
            for (int j = 0; j < 4; j++) acc[mi][ni][j] = 0.f;

    int ntile = K >> 5;

    {
        #pragma unroll
        for (int j = 0; j < 4; j++)
            cpasync16(As + a_r * AS_STRIDE + a_c + j * 4, a_g + j * 4);
        const float* w_g = W + (size_t)b_r * N + colBase + b_c;
        #pragma unroll
        for (int j = 0; j < 4; j++)
            cpasync16(Bs + b_r * BS_STRIDE + b_c + j * 32, w_g + j * 32);
        CP_COMMIT();
    }

    for (int t = 0; t < ntile; t++){
        if (t + 1 < ntile){
            int st = (t + 1) & 1;
            float* as = As + st * 128 * AS_STRIDE;
            float* bs = Bs + st * 32 * BS_STRIDE;
            int k0 = (t + 1) << 5;
            #pragma unroll
            for (int j = 0; j < 4; j++)
                cpasync16(as + a_r * AS_STRIDE + a_c + j * 4, a_g + k0 + j * 4);
            const float* w_g = W + (size_t)(k0 + b_r) * N + colBase + b_c;
            #pragma unroll
            for (int j = 0; j < 4; j++)
                cpasync16(bs + b_r * BS_STRIDE + b_c + j * 32, w_g + j * 32);
            CP_COMMIT();
            CP_WAIT(1);
        } else {
            CP_WAIT(0);
        }
        __syncthreads();

        int st = t & 1;
        const float* as = As + st * 128 * AS_STRIDE;
        const float* bs = Bs + st * 32 * BS_STRIDE;
        #pragma unroll
        for (int ks = 0; ks < 4; ks++){
            int kb = ks * 8;
            uint32_t af[2][4], bf[8][2];
            #pragma unroll
            for (int mi = 0; mi < 2; mi++){
                int m0 = warpRow * 32 + mi * 16;
                const float* ar0 = as + (m0 + gid) * AS_STRIDE + kb + tig;
                const float* ar1 = as + (m0 + gid + 8) * AS_STRIDE + kb + tig;
                af[mi][0] = f2tf32(ar0[0]);
                af[mi][1] = f2tf32(ar1[0]);
                af[mi][2] = f2tf32(ar0[4]);
                af[mi][3] = f2tf32(ar1[4]);
            }
            #pragma unroll
            for (int ni = 0; ni < 8; ni++){
                int n0 = warpCol * 64 + ni * 8;
                bf[ni][0] = f2tf32(bs[(kb + tig) * BS_STRIDE + n0 + gid]);
                bf[ni][1] = f2tf32(bs[(kb + tig + 4) * BS_STRIDE + n0 + gid]);
            }
            #pragma unroll
            for (int mi = 0; mi < 2; mi++)
                #pragma unroll
                for (int ni = 0; ni < 8; ni++)
                    mma_tf32(acc[mi][ni], af[mi], bf[ni]);
        }
        __syncthreads();
    }

    #pragma unroll
    for (int mi = 0; mi < 2; mi++){
        int r0 = rowBase + warpRow * 32 + mi * 16 + gid;
        #pragma unroll
        for (int ni = 0; ni < 8; ni++){
            int cc = colBase + warpCol * 64 + ni * 8 + tig * 2;
            float b0 = bias[cc], b1 = bias[cc + 1];
            float v0 = acc[mi][ni][0] + b0, v1 = acc[mi][ni][1] + b1;
            float v2 = acc[mi][ni][2] + b0, v3 = acc[mi][ni][3] + b1;
            if (act == 1){
                v0 = gelu_tanh(v0); v1 = gelu_tanh(v1);
                v2 = gelu_tanh(v2); v3 = gelu_tanh(v3);
            }
            *(float2*)&C[(size_t)r0 * N + cc] = make_float2(v0, v1);
            *(float2*)&C[(size_t)(r0 + 8) * N + cc] = make_float2(v2, v3);
        }
    }
}

// ---------------- attention: tf32 tensor-core flash attention, RNA rounding ---
#define ATT_SMEM ((128*68 + 64*72 + 64*72 + 8*16*72 + 256) * 4)
__global__ void __launch_bounds__(256, 2)
attn3_kernel(const float* __restrict__ qkv,
             const int* __restrict__ amask,
             float* __restrict__ out){
    extern __shared__ float sm[];
    float* Qs = sm;                   // 128*68
    float* Kt = Qs + 128 * 68;        // 64*72
    float* Vs = Kt + 64 * 72;         // 64*72
    float* Ps = Vs + 64 * 72;         // 8*16*72
    float* bs = Ps + 8 * 16 * 72;     // 256
    int tid = threadIdx.x, w = tid >> 5, lane = tid & 31;
    int gid = lane >> 2, tig = lane & 3;
    int qb = blockIdx.x * 128, h = blockIdx.y, b = blockIdx.z;
    const size_t rs = 3 * HID;
    const float* base = qkv + (size_t)b * SEQ * rs;
    float* Pw = Ps + w * 16 * 72;
    int m0 = w * 16;

    bs[tid] = (1.0f - (float)amask[b * SEQ + tid]) * -1e9f;

    // load Q tile, pre-scaled by 1/sqrt(64)
    {
        int r = tid >> 1, c0 = (tid & 1) * 32;
        const float* src = base + (size_t)(qb + r) * rs + h * HD + c0;
        float* dst = Qs + r * 68 + c0;
        #pragma unroll
        for (int j = 0; j < 8; j++){
            float4 v = *(const float4*)(src + j * 4);
            dst[j*4+0] = v.x * 0.125f; dst[j*4+1] = v.y * 0.125f;
            dst[j*4+2] = v.z * 0.125f; dst[j*4+3] = v.w * 0.125f;
        }
    }

    float of[8][4];
    #pragma unroll
    for (int ni = 0; ni < 8; ni++)
        #pragma unroll
        for (int j = 0; j < 4; j++) of[ni][j] = 0.f;
    float mrow0 = -1e30f, mrow1 = -1e30f, lrow0 = 0.f, lrow1 = 0.f;

    for (int c = 0; c < 4; c++){
        __syncthreads();
        {   // load K chunk (transposed to d-major) + V chunk (natural)
            int k = tid >> 2, d0 = (tid & 3) * 16;
            const float* ks = base + (size_t)(c * 64 + k) * rs + HID + h * HD + d0;
            const float* vs = base + (size_t)(c * 64 + k) * rs + 2 * HID + h * HD + d0;
            #pragma unroll
            for (int j = 0; j < 4; j++){
                float4 kv = *(const float4*)(ks + j * 4);
                Kt[(d0 + j*4 + 0) * 72 + k] = kv.x;
                Kt[(d0 + j*4 + 1) * 72 + k] = kv.y;
                Kt[(d0 + j*4 + 2) * 72 + k] = kv.z;
                Kt[(d0 + j*4 + 3) * 72 + k] = kv.w;
                *(float4*)(Vs + k * 72 + d0 + j * 4) = *(const float4*)(vs + j * 4);
            }
        }
        __syncthreads();

        // ---- S = Q @ K^T ----
        float sc[8][4];
        #pragma unroll
        for (int ni = 0; ni < 8; ni++)
            #pragma unroll
            for (int j = 0; j < 4; j++) sc[ni][j] = 0.f;
        #pragma unroll
        for (int ks = 0; ks < 8; ks++){
            int kb = ks * 8;
            uint32_t a[4];
            a[0] = f2tf32(Qs[(m0 + gid) * 68 + kb + tig]);
            a[1] = f2tf32(Qs[(m0 + gid + 8) * 68 + kb + tig]);
            a[2] = f2tf32(Qs[(m0 + gid) * 68 + kb + tig + 4]);
            a[3] = f2tf32(Qs[(m0 + gid + 8) * 68 + kb + tig + 4]);
            #pragma unroll
            for (int ni = 0; ni < 8; ni++){
                int n0 = ni * 8;
                uint32_t bf[2];
                bf[0] = f2tf32(Kt[(kb + tig) * 72 + n0 + gid]);
                bf[1] = f2tf32(Kt[(kb + tig + 4) * 72 + n0 + gid]);
                mma_tf32(sc[ni], a, bf);
            }
        }

        // ---- online softmax (rows gid and gid+8; cols tig*2, tig*2+1) ----
        float mx0 = -1e30f, mx1 = -1e30f;
        #pragma unroll
        for (int ni = 0; ni < 8; ni++){
            int key = c * 64 + ni * 8 + tig * 2;
            float b0 = bs[key], b1 = bs[key + 1];
            sc[ni][0] += b0; sc[ni][1] += b1;
            sc[ni][2] += b0; sc[ni][3] += b1;
            mx0 = fmaxf(mx0, fmaxf(sc[ni][0], sc[ni][1]));
            mx1 = fmaxf(mx1, fmaxf(sc[ni][2], sc[ni][3]));
        }
        mx0 = fmaxf(mx0, __shfl_xor_sync(0xffffffffu, mx0, 1));
        mx0 = fmaxf(mx0, __shfl_xor_sync(0xffffffffu, mx0, 2));
        mx1 = fmaxf(mx1, __shfl_xor_sync(0xffffffffu, mx1, 1));
        mx1 = fmaxf(mx1, __shfl_xor_sync(0xffffffffu, mx1, 2));
        float nm0 = fmaxf(mrow0, mx0), nm1 = fmaxf(mrow1, mx1);
        float corr0 = __expf(mrow0 - nm0), corr1 = __expf(mrow1 - nm1);
        float sum0 = 0.f, sum1 = 0.f;
        #pragma unroll
        for (int ni = 0; ni < 8; ni++){
            float p0 = __expf(sc[ni][0] - nm0);
            float p1 = __expf(sc[ni][1] - nm0);
            float p2 = __expf(sc[ni][2] - nm1);
            float p3 = __expf(sc[ni][3] - nm1);
            sum0 += p0 + p1; sum1 += p2 + p3;
            int n0 = ni * 8 + tig * 2;
            *(float2*)(Pw + gid * 72 + n0)       = make_float2(p0, p1);
            *(float2*)(Pw + (gid + 8) * 72 + n0) = make_float2(p2, p3);
        }
        sum0 += __shfl_xor_sync(0xffffffffu, sum0, 1);
        sum0 += __shfl_xor_sync(0xffffffffu, sum0, 2);
        sum1 += __shfl_xor_sync(0xffffffffu, sum1, 1);
        sum1 += __shfl_xor_sync(0xffffffffu, sum1, 2);
        lrow0 = lrow0 * corr0 + sum0;
        lrow1 = lrow1 * corr1 + sum1;
        mrow0 = nm0; mrow1 = nm1;
        #pragma unroll
        for (int ni = 0; ni < 8; ni++){
            of[ni][0] *= corr0; of[ni][1] *= corr0;
            of[ni][2] *= corr1; of[ni][3] *= corr1;
        }
        __syncwarp();

        // ---- O += P @ V ----
        #pragma unroll
        for (int ks = 0; ks < 8; ks++){
            int kb = ks * 8;
            uint32_t a[4];
            a[0] = f2tf32(Pw[gid * 72 + kb + tig]);
            a[1] = f2tf32(Pw[(gid + 8) * 72 + kb + tig]);
            a[2] = f2tf32(Pw[gid * 72 + kb + tig + 4]);
            a[3] = f2tf32(Pw[(gid + 8) * 72 + kb + tig + 4]);
            #pragma unroll
            for (int ni = 0; ni < 8; ni++){
                int n0 = ni * 8;
                uint32_t bf[2];
                bf[0] = f2tf32(Vs[(kb + tig) * 72 + n0 + gid]);
                bf[1] = f2tf32(Vs[(kb + tig + 4) * 72 + n0 + gid]);
                mma_tf32(of[ni], a, bf);
            }
        }
        __syncwarp();
    }

    // ---- normalize + write ----
    float inv0 = 1.0f / lrow0, inv1 = 1.0f / lrow1;
    int q0 = qb + m0 + gid, q1 = q0 + 8;
    #pragma unroll
    for (int ni = 0; ni < 8; ni++){
        int d = ni * 8 + tig * 2;
        *(float2*)&out[(size_t)(b * SEQ + q0) * HID + h * HD + d] =
            make_float2(of[ni][0] * inv0, of[ni][1] * inv0);
        *(float2*)&out[(size_t)(b * SEQ + q1) * HID + h * HD + d] =
            make_float2(of[ni][2] * inv1, of[ni][3] * inv1);
    }
}

// ---------------- classifier ----------------
__global__ void cls_kernel(const float* __restrict__ x,
                           const float* __restrict__ W,
                           const float* __restrict__ bias,
                           float* __restrict__ logits){
    __shared__ float xs[HID];
    int tok = blockIdx.x;
    for (int d = threadIdx.x; d < HID; d += blockDim.x)
        xs[d] = x[(size_t)tok * HID + d];
    __syncthreads();
    int w = threadIdx.x >> 5, lane = threadIdx.x & 31;
    float acc = 0.f;
    for (int d = lane; d < HID; d += 32)
        acc = fmaf(xs[d], W[d * NT + w], acc);
    acc = warpReduceSum(acc);
    if (lane == 0) logits[tok * NT + w] = acc + bias[w];
}

// ---------------- CRF ----------------
__global__ void crf_kernel(const float* __restrict__ logits,
                           const int* __restrict__ labels,
                           const float* __restrict__ cstart,
                           const float* __restrict__ cend,
                           const float* __restrict__ ctrans,
                           float* __restrict__ res){
    __shared__ float score[NT];
    __shared__ float tr[NT * NT];
    __shared__ float st[NT], en[NT];
    int b = blockIdx.x, tid = threadIdx.x;
    for (int i = tid; i < NT * NT; i += 32) tr[i] = ctrans[i];
    if (tid < NT){ st[tid] = cstart[tid]; en[tid] = cend[tid]; }
    const float* lg = logits + (size_t)b * SEQ * NT;
    const int* lab = labels + b * SEQ;
    if (tid < NT) score[tid] = st[tid] + lg[tid];
    __syncwarp();
    for (int s = 1; s < SEQ; s++){
        float nxt = 0.f;
        if (tid < NT){
            float m = -INFINITY;
            #pragma unroll
            for (int i = 0; i < NT; i++) m = fmaxf(m, score[i] + tr[i * NT + tid]);
            float sum = 0.f;
            #pragma unroll
            for (int i = 0; i < NT; i++) sum += expf(score[i] + tr[i * NT + tid] - m);
            nxt = m + logf(sum) + lg[s * NT + tid];
        }
        bool msk = (lab[s] != -100);
        __syncwarp();
        if (tid < NT && msk) score[tid] = nxt;
        __syncwarp();
    }
    if (tid == 0){
        float m = -INFINITY;
        for (int t = 0; t < NT; t++) m = fmaxf(m, score[t] + en[t]);
        float sum = 0.f;
        for (int t = 0; t < NT; t++) sum += expf(score[t] + en[t] - m);
        float denom = m + logf(sum);
        int l0 = lab[0];
        int tag_prev = (l0 == -100) ? 0 : l0;
        float num = st[tag_prev] + lg[tag_prev];
        int cnt = 1;
        for (int s = 1; s < SEQ; s++){
            int ls = lab[s];
            bool msk = (ls != -100);
            int tg = msk ? ls : 0;
            if (msk){
                num += tr[tag_prev * NT + tg] + lg[s * NT + tg];
                cnt++;
            }
            tag_prev = tg;
        }
        int seq_end = cnt - 1;
        int le = lab[seq_end];
        int last_tag = (le == -100) ? 0 : le;
        num += en[last_tag];
        res[b] = num - denom;
    }
}

// ---------------- finalize ----------------
__global__ void finalize_kernel(const float* __restrict__ res,
                                const float* __restrict__ logits,
                                float* __restrict__ out, int nlog){
    int idx = blockIdx.x * blockDim.x + threadIdx.x;
    if (idx == 0){
        float s = 0.f;
        for (int b = 0; b < BSZ; b++) s += res[b];
        out[0] = -s / BSZ;
    }
    if (idx < nlog) out[1 + idx] = logits[idx];
}

// ---------------- launch ----------------
extern "C" void kernel_launch(void* const* d_in, const int* in_sizes, int n_in,
                              void* d_out, int out_size){
    const int*   input_ids = (const int*)  d_in[0];
    const int*   amask     = (const int*)  d_in[1];
    const int*   labels    = (const int*)  d_in[2];
    const float* word_emb  = (const float*)d_in[3];
    const float* pos_emb   = (const float*)d_in[4];
    const float* emb_ln_s  = (const float*)d_in[5];
    const float* emb_ln_b  = (const float*)d_in[6];
    const float* Wqkv      = (const float*)d_in[7];
    const float* bqkv      = (const float*)d_in[8];
    const float* Wo        = (const float*)d_in[9];
    const float* bo        = (const float*)d_in[10];
    const float* ln1_s     = (const float*)d_in[11];
    const float* ln1_b     = (const float*)d_in[12];
    const float* Wff1      = (const float*)d_in[13];
    const float* bff1      = (const float*)d_in[14];
    const float* Wff2      = (const float*)d_in[15];
    const float* bff2      = (const float*)d_in[16];
    const float* ln2_s     = (const float*)d_in[17];
    const float* ln2_b     = (const float*)d_in[18];
    const float* Wcls      = (const float*)d_in[19];
    const float* bcls      = (const float*)d_in[20];
    const float* crf_start = (const float*)d_in[21];
    const float* crf_end   = (const float*)d_in[22];
    const float* crf_trans = (const float*)d_in[23];

    float *x, *h1, *tmp, *qkv, *attn, *ffn, *logits, *res;
    cudaGetSymbolAddress((void**)&x,      g_x);
    cudaGetSymbolAddress((void**)&h1,     g_h1);
    cudaGetSymbolAddress((void**)&tmp,    g_tmp);
    cudaGetSymbolAddress((void**)&qkv,    g_qkv);
    cudaGetSymbolAddress((void**)&attn,   g_attn);
    cudaGetSymbolAddress((void**)&ffn,    g_ffn);
    cudaGetSymbolAddress((void**)&logits, g_logits);
    cudaGetSymbolAddress((void**)&res,    g_res);

    static int smem_set = 0;
    if (!smem_set){
        cudaFuncSetAttribute(attn3_kernel,
                             cudaFuncAttributeMaxDynamicSharedMemorySize, ATT_SMEM);
        cudaFuncSetAttribute(gemm_tc,
                             cudaFuncAttributeMaxDynamicSharedMemorySize, GEMM_SMEM);
        smem_set = 1;
    }

    embed_kernel<<<TOK, 256>>>(input_ids, word_emb, pos_emb, emb_ln_s, emb_ln_b, x);

    for (int l = 0; l < NLAYERS; l++){
        const float* wqkv = Wqkv + (size_t)l * HID * 3 * HID;
        const float* bq   = bqkv + (size_t)l * 3 * HID;
        const float* wo   = Wo   + (size_t)l * HID * HID;
        const float* bo_  = bo   + (size_t)l * HID;
        const float* s1   = ln1_s + (size_t)l * HID;
        const float* b1   = ln1_b + (size_t)l * HID;
        const float* w1   = Wff1 + (size_t)l * HID * FFN;
        const float* bf1  = bff1 + (size_t)l * FFN;
        const float* w2   = Wff2 + (size_t)l * FFN * HID;
        const float* bf2  = bff2 + (size_t)l * HID;
        const float* s2   = ln2_s + (size_t)l * HID;
        const float* b2   = ln2_b + (size_t)l * HID;

        gemm_tc<<<dim3(3 * HID / 128, TOK / 128), 256, GEMM_SMEM>>>(x, wqkv, bq, qkv, TOK, 3 * HID, HID, 0);
        attn3_kernel<<<dim3(SEQ / 128, NH, BSZ), 256, ATT_SMEM>>>(qkv, amask, attn);
        gemm_tc<<<dim3(HID / 128, TOK / 128), 256, GEMM_SMEM>>>(attn, wo, bo_, tmp, TOK, HID, HID, 0);
        ln_residual_kernel<<<TOK, 256>>>(x, tmp, s1, b1, h1);
        gemm_tc<<<dim3(FFN / 128, TOK / 128), 256, GEMM_SMEM>>>(h1, w1, bf1, ffn, TOK, FFN, HID, 1);
        gemm_tc<<<dim3(HID / 128, TOK / 128), 256, GEMM_SMEM>>>(ffn, w2, bf2, tmp, TOK, HID, FFN, 0);
        ln_residual_kernel<<<TOK, 256>>>(h1, tmp, s2, b2, x);
    }

    cls_kernel<<<TOK, 288>>>(x, Wcls, bcls, logits);
    crf_kernel<<<BSZ, 32>>>(logits, labels, crf_start, crf_end, crf_trans, res);
    int nlog = TOK * NT;
    finalize_kernel<<<(nlog + 256) / 256, 256>>>(res, logits, (float*)d_out, nlog);
}

// round 6
// speedup vs baseline: 7.2952x; 1.0239x over previous
#include <cuda_runtime.h>
#include <cuda_bf16.h>
#include <math.h>
#include <stdint.h>

#define BSZ 16
#define SEQ 256
#define HID 768
#define TOK (BSZ*SEQ)      // 4096
#define FFN 3072
#define NH 12
#define HD 64
#define NT 9
#define NLAYERS 6

// weight counts
#define WQKV_CNT (NLAYERS*HID*3*HID)        // 10,616,832
#define WO_CNT   (NLAYERS*HID*HID)          // 3,538,944
#define WFF1_CNT (NLAYERS*HID*FFN)          // 14,155,776
#define WFF2_CNT (NLAYERS*FFN*HID)          // 14,155,776
#define WTOT_CNT (WQKV_CNT+WO_CNT+WFF1_CNT+WFF2_CNT)

// ---------------- scratch (static device globals; no allocations) ----------------
__device__ float g_x[TOK*HID];
__device__ float g_h1[TOK*HID];
__device__ float g_tmp[TOK*HID];
__device__ float g_qkv[TOK*3*HID];
__device__ float g_attn[TOK*HID];
__device__ float g_ffn[(size_t)TOK*FFN];
__device__ float g_logits[TOK*NT];
__device__ float g_res[BSZ];
__device__ float g_wrnd[(size_t)WTOT_CNT];   // tf32-rounded weights

// ---------------- reductions ----------------
__device__ __forceinline__ float warpReduceSum(float v){
    #pragma unroll
    for (int o = 16; o; o >>= 1) v += __shfl_xor_sync(0xffffffffu, v, o);
    return v;
}
__device__ float blockReduceSum(float v, float* sh){
    __syncthreads();
    int lane = threadIdx.x & 31, wid = threadIdx.x >> 5;
    v = warpReduceSum(v);
    if (lane == 0) sh[wid] = v;
    __syncthreads();
    int nw = blockDim.x >> 5;
    v = (threadIdx.x < nw) ? sh[threadIdx.x] : 0.0f;
    if (wid == 0) v = warpReduceSum(v);
    if (threadIdx.x == 0) sh[0] = v;
    __syncthreads();
    return sh[0];
}

__device__ __forceinline__ float gelu_tanh(float x){
    float x3 = x * x * x;
    return 0.5f * x * (1.0f + tanhf(0.7978845608028654f * (x + 0.044715f * x3)));
}

// ---------------- tf32 / async helpers ----------------
__device__ __forceinline__ uint32_t f2tf32(float f){
    uint32_t r; asm("cvt.rna.tf32.f32 %0, %1;" : "=r"(r) : "f"(f)); return r;
}
__device__ __forceinline__ void mma_tf32(float* c, const uint32_t* a, const uint32_t* b){
    asm volatile(
        "mma.sync.aligned.m16n8k8.row.col.f32.tf32.tf32.f32 "
        "{%0,%1,%2,%3},{%4,%5,%6,%7},{%8,%9},{%0,%1,%2,%3};"
        : "+f"(c[0]), "+f"(c[1]), "+f"(c[2]), "+f"(c[3])
        : "r"(a[0]), "r"(a[1]), "r"(a[2]), "r"(a[3]), "r"(b[0]), "r"(b[1]));
}
__device__ __forceinline__ void cpasync16(float* smem, const float* g){
    uint32_t s = (uint32_t)__cvta_generic_to_shared(smem);
    asm volatile("cp.async.cg.shared.global [%0], [%1], 16;" :: "r"(s), "l"(g));
}
#define CP_COMMIT() asm volatile("cp.async.commit_group;")
#define CP_WAIT(n)  asm volatile("cp.async.wait_group %0;" :: "n"(n))

// ---------------- weight rounding: dst = tf32_rna(src) ----------------
__global__ void round_w_kernel(const float* __restrict__ src,
                               float* __restrict__ dst, int n){
    int i = (blockIdx.x * blockDim.x + threadIdx.x) * 4;
    if (i < n){
        float4 v = *(const float4*)(src + i);
        v.x = __uint_as_float(f2tf32(v.x));
        v.y = __uint_as_float(f2tf32(v.y));
        v.z = __uint_as_float(f2tf32(v.z));
        v.w = __uint_as_float(f2tf32(v.w));
        *(float4*)(dst + i) = v;
    }
}

// ---------------- embedding + LN ----------------
__global__ void embed_kernel(const int* __restrict__ ids,
                             const float* __restrict__ we,
                             const float* __restrict__ pe,
                             const float* __restrict__ gamma,
                             const float* __restrict__ beta,
                             float* __restrict__ out){
    __shared__ float sh[32];
    int tok = blockIdx.x;
    int sI = tok % SEQ;
    int id = ids[tok];
    const float* wrow = we + (size_t)id * HID;
    const float* prow = pe + (size_t)sI * HID;
    float vals[3]; float lsum = 0.f;
    #pragma unroll
    for (int i = 0; i < 3; i++){
        int d = threadIdx.x + i * 256;
        float v = wrow[d] + prow[d];
        vals[i] = v; lsum += v;
    }
    float mean = blockReduceSum(lsum, sh) * (1.0f / HID);
    float lss = 0.f;
    #pragma unroll
    for (int i = 0; i < 3; i++){ float d0 = vals[i] - mean; lss += d0 * d0; }
    float var = blockReduceSum(lss, sh) * (1.0f / HID);
    float rstd = rsqrtf(var + 1e-12f);
    float* orow = out + (size_t)tok * HID;
    #pragma unroll
    for (int i = 0; i < 3; i++){
        int d = threadIdx.x + i * 256;
        orow[d] = (vals[i] - mean) * rstd * gamma[d] + beta[d];
    }
}

// ---------------- residual + LN ----------------
__global__ void ln_residual_kernel(const float* __restrict__ a,
                                   const float* __restrict__ c,
                                   const float* __restrict__ gamma,
                                   const float* __restrict__ beta,
                                   float* __restrict__ out){
    __shared__ float sh[32];
    int tok = blockIdx.x;
    const float* ar = a + (size_t)tok * HID;
    const float* cr = c + (size_t)tok * HID;
    float vals[3]; float lsum = 0.f;
    #pragma unroll
    for (int i = 0; i < 3; i++){
        int d = threadIdx.x + i * 256;
        float v = ar[d] + cr[d];
        vals[i] = v; lsum += v;
    }
    float mean = blockReduceSum(lsum, sh) * (1.0f / HID);
    float lss = 0.f;
    #pragma unroll
    for (int i = 0; i < 3; i++){ float d0 = vals[i] - mean; lss += d0 * d0; }
    float var = blockReduceSum(lss, sh) * (1.0f / HID);
    float rstd = rsqrtf(var + 1e-12f);
    float* orow = out + (size_t)tok * HID;
    #pragma unroll
    for (int i = 0; i < 3; i++){
        int d = threadIdx.x + i * 256;
        orow[d] = (vals[i] - mean) * rstd * gamma[d] + beta[d];
    }
}

// ---------------- tf32 TC GEMM: 3-stage cp.async, pre-rounded weights --------
#define AS_STRIDE 36
#define BS_STRIDE 136
#define NSTAGE 3
#define STAGE_FLOATS (128*AS_STRIDE + 32*BS_STRIDE)
#define GEMM_SMEM (NSTAGE * STAGE_FLOATS * 4)

__device__ __forceinline__ void gemm_load_tile(const float* __restrict__ A,
                                               const float* __restrict__ W,
                                               float* as, float* bs,
                                               int a_r, int a_c, int b_r, int b_c,
                                               int rowBase, int colBase,
                                               int k0, int K, int N){
    const float* ag = A + (size_t)(rowBase + a_r) * K + k0 + a_c;
    #pragma unroll
    for (int j = 0; j < 4; j++)
        cpasync16(as + a_r * AS_STRIDE + a_c + j * 4, ag + j * 4);
    const float* wg = W + (size_t)(k0 + b_r) * N + colBase + b_c;
    #pragma unroll
    for (int j = 0; j < 4; j++)
        cpasync16(bs + b_r * BS_STRIDE + b_c + j * 32, wg + j * 32);
}

__global__ void __launch_bounds__(256, 2)
gemm_tc(const float* __restrict__ A,
        const float* __restrict__ W,   // pre-rounded to tf32
        const float* __restrict__ bias,
        float* __restrict__ C,
        int M, int N, int K, int act){
    extern __shared__ float sm[];

    int tid = threadIdx.x;
    int wid = tid >> 5, lane = tid & 31;
    int warpRow = wid >> 1, warpCol = wid & 1;
    int gid = lane >> 2, tig = lane & 3;
    int rowBase = blockIdx.y * 128, colBase = blockIdx.x * 128;

    int a_r = tid >> 1;
    int a_c = (tid & 1) * 16;
    int b_r = tid >> 3;
    int b_c = (tid & 7) * 4;

    float acc[2][8][4];
    #pragma unroll
    for (int mi = 0; mi < 2; mi++)
        #pragma unroll
        for (int ni = 0; ni < 8; ni++)
            #pragma unroll
            for (int j = 0; j < 4; j++) acc[mi][ni][j] = 0.f;

    int ntile = K >> 5;

    // prologue: tiles 0,1
    #pragma unroll
    for (int s = 0; s < 2; s++){
        float* as = sm + s * STAGE_FLOATS;
        float* bs = as + 128 * AS_STRIDE;
        gemm_load_tile(A, W, as, bs, a_r, a_c, b_r, b_c, rowBase, colBase, s << 5, K, N);
        CP_COMMIT();
    }

    int st = 0;
    for (int t = 0; t < ntile; t++){
        if (t + 1 < ntile) { CP_WAIT(1); } else { CP_WAIT(0); }
        __syncthreads();

        // prefetch t+2 into stage (t+2)%3 (clobbers stage of t-1; barrier above protects)
        if (t + 2 < ntile){
            int ps = st + 2; if (ps >= NSTAGE) ps -= NSTAGE;
            float* as = sm + ps * STAGE_FLOATS;
            float* bs = as + 128 * AS_STRIDE;
            gemm_load_tile(A, W, as, bs, a_r, a_c, b_r, b_c, rowBase, colBase, (t + 2) << 5, K, N);
            CP_COMMIT();
        }

        const float* as = sm + st * STAGE_FLOATS;
        const float* bs = as + 128 * AS_STRIDE;
        #pragma unroll
        for (int ks = 0; ks < 4; ks++){
            int kb = ks * 8;
            uint32_t af[2][4], bf[8][2];
            #pragma unroll
            for (int mi = 0; mi < 2; mi++){
                int m0 = warpRow * 32 + mi * 16;
                const float* ar0 = as + (m0 + gid) * AS_STRIDE + kb + tig;
                const float* ar1 = as + (m0 + gid + 8) * AS_STRIDE + kb + tig;
                af[mi][0] = f2tf32(ar0[0]);
                af[mi][1] = f2tf32(ar1[0]);
                af[mi][2] = f2tf32(ar0[4]);
                af[mi][3] = f2tf32(ar1[4]);
            }
            #pragma unroll
            for (int ni = 0; ni < 8; ni++){
                int n0 = warpCol * 64 + ni * 8;
                bf[ni][0] = __float_as_uint(bs[(kb + tig) * BS_STRIDE + n0 + gid]);
                bf[ni][1] = __float_as_uint(bs[(kb + tig + 4) * BS_STRIDE + n0 + gid]);
            }
            #pragma unroll
            for (int mi = 0; mi < 2; mi++)
                #pragma unroll
                for (int ni = 0; ni < 8; ni++)
                    mma_tf32(acc[mi][ni], af[mi], bf[ni]);
        }
        if (++st >= NSTAGE) st = 0;
    }

    #pragma unroll
    for (int mi = 0; mi < 2; mi++){
        int r0 = rowBase + warpRow * 32 + mi * 16 + gid;
        #pragma unroll
        for (int ni = 0; ni < 8; ni++){
            int cc = colBase + warpCol * 64 + ni * 8 + tig * 2;
            float b0 = bias[cc], b1 = bias[cc + 1];
            float v0 = acc[mi][ni][0] + b0, v1 = acc[mi][ni][1] + b1;
            float v2 = acc[mi][ni][2] + b0, v3 = acc[mi][ni][3] + b1;
            if (act == 1){
                v0 = gelu_tanh(v0); v1 = gelu_tanh(v1);
                v2 = gelu_tanh(v2); v3 = gelu_tanh(v3);
            }
            *(float2*)&C[(size_t)r0 * N + cc] = make_float2(v0, v1);
            *(float2*)&C[(size_t)(r0 + 8) * N + cc] = make_float2(v2, v3);
        }
    }
}

// ---------------- attention: tf32 tensor-core flash attention (R5) -----------
#define ATT_SMEM ((128*68 + 64*72 + 64*72 + 8*16*72 + 256) * 4)
__global__ void __launch_bounds__(256, 2)
attn3_kernel(const float* __restrict__ qkv,
             const int* __restrict__ amask,
             float* __restrict__ out){
    extern __shared__ float sm[];
    float* Qs = sm;
    float* Kt = Qs + 128 * 68;
    float* Vs = Kt + 64 * 72;
    float* Ps = Vs + 64 * 72;
    float* bs = Ps + 8 * 16 * 72;
    int tid = threadIdx.x, w = tid >> 5, lane = tid & 31;
    int gid = lane >> 2, tig = lane & 3;
    int qb = blockIdx.x * 128, h = blockIdx.y, b = blockIdx.z;
    const size_t rs = 3 * HID;
    const float* base = qkv + (size_t)b * SEQ * rs;
    float* Pw = Ps + w * 16 * 72;
    int m0 = w * 16;

    bs[tid] = (1.0f - (float)amask[b * SEQ + tid]) * -1e9f;

    {
        int r = tid >> 1, c0 = (tid & 1) * 32;
        const float* src = base + (size_t)(qb + r) * rs + h * HD + c0;
        float* dst = Qs + r * 68 + c0;
        #pragma unroll
        for (int j = 0; j < 8; j++){
            float4 v = *(const float4*)(src + j * 4);
            dst[j*4+0] = v.x * 0.125f; dst[j*4+1] = v.y * 0.125f;
            dst[j*4+2] = v.z * 0.125f; dst[j*4+3] = v.w * 0.125f;
        }
    }

    float of[8][4];
    #pragma unroll
    for (int ni = 0; ni < 8; ni++)
        #pragma unroll
        for (int j = 0; j < 4; j++) of[ni][j] = 0.f;
    float mrow0 = -1e30f, mrow1 = -1e30f, lrow0 = 0.f, lrow1 = 0.f;

    for (int c = 0; c < 4; c++){
        __syncthreads();
        {
            int k = tid >> 2, d0 = (tid & 3) * 16;
            const float* ks = base + (size_t)(c * 64 + k) * rs + HID + h * HD + d0;
            const float* vs = base + (size_t)(c * 64 + k) * rs + 2 * HID + h * HD + d0;
            #pragma unroll
            for (int j = 0; j < 4; j++){
                float4 kv = *(const float4*)(ks + j * 4);
                Kt[(d0 + j*4 + 0) * 72 + k] = kv.x;
                Kt[(d0 + j*4 + 1) * 72 + k] = kv.y;
                Kt[(d0 + j*4 + 2) * 72 + k] = kv.z;
                Kt[(d0 + j*4 + 3) * 72 + k] = kv.w;
                *(float4*)(Vs + k * 72 + d0 + j * 4) = *(const float4*)(vs + j * 4);
            }
        }
        __syncthreads();

        float sc[8][4];
        #pragma unroll
        for (int ni = 0; ni < 8; ni++)
            #pragma unroll
            for (int j = 0; j < 4; j++) sc[ni][j] = 0.f;
        #pragma unroll
        for (int ks = 0; ks < 8; ks++){
            int kb = ks * 8;
            uint32_t a[4];
            a[0] = f2tf32(Qs[(m0 + gid) * 68 + kb + tig]);
            a[1] = f2tf32(Qs[(m0 + gid + 8) * 68 + kb + tig]);
            a[2] = f2tf32(Qs[(m0 + gid) * 68 + kb + tig + 4]);
            a[3] = f2tf32(Qs[(m0 + gid + 8) * 68 + kb + tig + 4]);
            #pragma unroll
            for (int ni = 0; ni < 8; ni++){
                int n0 = ni * 8;
                uint32_t bf[2];
                bf[0] = f2tf32(Kt[(kb + tig) * 72 + n0 + gid]);
                bf[1] = f2tf32(Kt[(kb + tig + 4) * 72 + n0 + gid]);
                mma_tf32(sc[ni], a, bf);
            }
        }

        float mx0 = -1e30f, mx1 = -1e30f;
        #pragma unroll
        for (int ni = 0; ni < 8; ni++){
            int key = c * 64 + ni * 8 + tig * 2;
            float b0 = bs[key], b1 = bs[key + 1];
            sc[ni][0] += b0; sc[ni][1] += b1;
            sc[ni][2] += b0; sc[ni][3] += b1;
            mx0 = fmaxf(mx0, fmaxf(sc[ni][0], sc[ni][1]));
            mx1 = fmaxf(mx1, fmaxf(sc[ni][2], sc[ni][3]));
        }
        mx0 = fmaxf(mx0, __shfl_xor_sync(0xffffffffu, mx0, 1));
        mx0 = fmaxf(mx0, __shfl_xor_sync(0xffffffffu, mx0, 2));
        mx1 = fmaxf(mx1, __shfl_xor_sync(0xffffffffu, mx1, 1));
        mx1 = fmaxf(mx1, __shfl_xor_sync(0xffffffffu, mx1, 2));
        float nm0 = fmaxf(mrow0, mx0), nm1 = fmaxf(mrow1, mx1);
        float corr0 = __expf(mrow0 - nm0), corr1 = __expf(mrow1 - nm1);
        float sum0 = 0.f, sum1 = 0.f;
        #pragma unroll
        for (int ni = 0; ni < 8; ni++){
            float p0 = __expf(sc[ni][0] - nm0);
            float p1 = __expf(sc[ni][1] - nm0);
            float p2 = __expf(sc[ni][2] - nm1);
            float p3 = __expf(sc[ni][3] - nm1);
            sum0 += p0 + p1; sum1 += p2 + p3;
            int n0 = ni * 8 + tig * 2;
            *(float2*)(Pw + gid * 72 + n0)       = make_float2(p0, p1);
            *(float2*)(Pw + (gid + 8) * 72 + n0) = make_float2(p2, p3);
        }
        sum0 += __shfl_xor_sync(0xffffffffu, sum0, 1);
        sum0 += __shfl_xor_sync(0xffffffffu, sum0, 2);
        sum1 += __shfl_xor_sync(0xffffffffu, sum1, 1);
        sum1 += __shfl_xor_sync(0xffffffffu, sum1, 2);
        lrow0 = lrow0 * corr0 + sum0;
        lrow1 = lrow1 * corr1 + sum1;
        mrow0 = nm0; mrow1 = nm1;
        #pragma unroll
        for (int ni = 0; ni < 8; ni++){
            of[ni][0] *= corr0; of[ni][1] *= corr0;
            of[ni][2] *= corr1; of[ni][3] *= corr1;
        }
        __syncwarp();

        #pragma unroll
        for (int ks = 0; ks < 8; ks++){
            int kb = ks * 8;
            uint32_t a[4];
            a[0] = f2tf32(Pw[gid * 72 + kb + tig]);
            a[1] = f2tf32(Pw[(gid + 8) * 72 + kb + tig]);
            a[2] = f2tf32(Pw[gid * 72 + kb + tig + 4]);
            a[3] = f2tf32(Pw[(gid + 8) * 72 + kb + tig + 4]);
            #pragma unroll
            for (int ni = 0; ni < 8; ni++){
                int n0 = ni * 8;
                uint32_t bf[2];
                bf[0] = f2tf32(Vs[(kb + tig) * 72 + n0 + gid]);
                bf[1] = f2tf32(Vs[(kb + tig + 4) * 72 + n0 + gid]);
                mma_tf32(of[ni], a, bf);
            }
        }
        __syncwarp();
    }

    float inv0 = 1.0f / lrow0, inv1 = 1.0f / lrow1;
    int q0 = qb + m0 + gid, q1 = q0 + 8;
    #pragma unroll
    for (int ni = 0; ni < 8; ni++){
        int d = ni * 8 + tig * 2;
        *(float2*)&out[(size_t)(b * SEQ + q0) * HID + h * HD + d] =
            make_float2(of[ni][0] * inv0, of[ni][1] * inv0);
        *(float2*)&out[(size_t)(b * SEQ + q1) * HID + h * HD + d] =
            make_float2(of[ni][2] * inv1, of[ni][3] * inv1);
    }
}

// ---------------- classifier ----------------
__global__ void cls_kernel(const float* __restrict__ x,
                           const float* __restrict__ W,
                           const float* __restrict__ bias,
                           float* __restrict__ logits){
    __shared__ float xs[HID];
    int tok = blockIdx.x;
    for (int d = threadIdx.x; d < HID; d += blockDim.x)
        xs[d] = x[(size_t)tok * HID + d];
    __syncthreads();
    int w = threadIdx.x >> 5, lane = threadIdx.x & 31;
    float acc = 0.f;
    for (int d = lane; d < HID; d += 32)
        acc = fmaf(xs[d], W[d * NT + w], acc);
    acc = warpReduceSum(acc);
    if (lane == 0) logits[tok * NT + w] = acc + bias[w];
}

// ---------------- CRF ----------------
__global__ void crf_kernel(const float* __restrict__ logits,
                           const int* __restrict__ labels,
                           const float* __restrict__ cstart,
                           const float* __restrict__ cend,
                           const float* __restrict__ ctrans,
                           float* __restrict__ res){
    __shared__ float score[NT];
    __shared__ float tr[NT * NT];
    __shared__ float st[NT], en[NT];
    int b = blockIdx.x, tid = threadIdx.x;
    for (int i = tid; i < NT * NT; i += 32) tr[i] = ctrans[i];
    if (tid < NT){ st[tid] = cstart[tid]; en[tid] = cend[tid]; }
    const float* lg = logits + (size_t)b * SEQ * NT;
    const int* lab = labels + b * SEQ;
    if (tid < NT) score[tid] = st[tid] + lg[tid];
    __syncwarp();
    for (int s = 1; s < SEQ; s++){
        float nxt = 0.f;
        if (tid < NT){
            float m = -INFINITY;
            #pragma unroll
            for (int i = 0; i < NT; i++) m = fmaxf(m, score[i] + tr[i * NT + tid]);
            float sum = 0.f;
            #pragma unroll
            for (int i = 0; i < NT; i++) sum += expf(score[i] + tr[i * NT + tid] - m);
            nxt = m + logf(sum) + lg[s * NT + tid];
        }
        bool msk = (lab[s] != -100);
        __syncwarp();
        if (tid < NT && msk) score[tid] = nxt;
        __syncwarp();
    }
    if (tid == 0){
        float m = -INFINITY;
        for (int t = 0; t < NT; t++) m = fmaxf(m, score[t] + en[t]);
        float sum = 0.f;
        for (int t = 0; t < NT; t++) sum += expf(score[t] + en[t] - m);
        float denom = m + logf(sum);
        int l0 = lab[0];
        int tag_prev = (l0 == -100) ? 0 : l0;
        float num = st[tag_prev] + lg[tag_prev];
        int cnt = 1;
        for (int s = 1; s < SEQ; s++){
            int ls = lab[s];
            bool msk = (ls != -100);
            int tg = msk ? ls : 0;
            if (msk){
                num += tr[tag_prev * NT + tg] + lg[s * NT + tg];
                cnt++;
            }
            tag_prev = tg;
        }
        int seq_end = cnt - 1;
        int le = lab[seq_end];
        int last_tag = (le == -100) ? 0 : le;
        num += en[last_tag];
        res[b] = num - denom;
    }
}

// ---------------- finalize ----------------
__global__ void finalize_kernel(const float* __restrict__ res,
                                const float* __restrict__ logits,
                                float* __restrict__ out, int nlog){
    int idx = blockIdx.x * blockDim.x + threadIdx.x;
    if (idx == 0){
        float s = 0.f;
        for (int b = 0; b < BSZ; b++) s += res[b];
        out[0] = -s / BSZ;
    }
    if (idx < nlog) out[1 + idx] = logits[idx];
}

// ---------------- launch ----------------
extern "C" void kernel_launch(void* const* d_in, const int* in_sizes, int n_in,
                              void* d_out, int out_size){
    const int*   input_ids = (const int*)  d_in[0];
    const int*   amask     = (const int*)  d_in[1];
    const int*   labels    = (const int*)  d_in[2];
    const float* word_emb  = (const float*)d_in[3];
    const float* pos_emb   = (const float*)d_in[4];
    const float* emb_ln_s  = (const float*)d_in[5];
    const float* emb_ln_b  = (const float*)d_in[6];
    const float* Wqkv      = (const float*)d_in[7];
    const float* bqkv      = (const float*)d_in[8];
    const float* Wo        = (const float*)d_in[9];
    const float* bo        = (const float*)d_in[10];
    const float* ln1_s     = (const float*)d_in[11];
    const float* ln1_b     = (const float*)d_in[12];
    const float* Wff1      = (const float*)d_in[13];
    const float* bff1      = (const float*)d_in[14];
    const float* Wff2      = (const float*)d_in[15];
    const float* bff2      = (const float*)d_in[16];
    const float* ln2_s     = (const float*)d_in[17];
    const float* ln2_b     = (const float*)d_in[18];
    const float* Wcls      = (const float*)d_in[19];
    const float* bcls      = (const float*)d_in[20];
    const float* crf_start = (const float*)d_in[21];
    const float* crf_end   = (const float*)d_in[22];
    const float* crf_trans = (const float*)d_in[23];

    float *x, *h1, *tmp, *qkv, *attn, *ffn, *logits, *res, *wrnd;
    cudaGetSymbolAddress((void**)&x,      g_x);
    cudaGetSymbolAddress((void**)&h1,     g_h1);
    cudaGetSymbolAddress((void**)&tmp,    g_tmp);
    cudaGetSymbolAddress((void**)&qkv,    g_qkv);
    cudaGetSymbolAddress((void**)&attn,   g_attn);
    cudaGetSymbolAddress((void**)&ffn,    g_ffn);
    cudaGetSymbolAddress((void**)&logits, g_logits);
    cudaGetSymbolAddress((void**)&res,    g_res);
    cudaGetSymbolAddress((void**)&wrnd,   g_wrnd);

    float* rWqkv = wrnd;
    float* rWo   = rWqkv + WQKV_CNT;
    float* rWff1 = rWo   + WO_CNT;
    float* rWff2 = rWff1 + WFF1_CNT;

    static int smem_set = 0;
    if (!smem_set){
        cudaFuncSetAttribute(attn3_kernel,
                             cudaFuncAttributeMaxDynamicSharedMemorySize, ATT_SMEM);
        cudaFuncSetAttribute(gemm_tc,
                             cudaFuncAttributeMaxDynamicSharedMemorySize, GEMM_SMEM);
        smem_set = 1;
    }

    // round all weights to tf32 (RNA) once per launch
    round_w_kernel<<<(WQKV_CNT/4 + 255)/256, 256>>>(Wqkv, rWqkv, WQKV_CNT);
    round_w_kernel<<<(WO_CNT  /4 + 255)/256, 256>>>(Wo,   rWo,   WO_CNT);
    round_w_kernel<<<(WFF1_CNT/4 + 255)/256, 256>>>(Wff1, rWff1, WFF1_CNT);
    round_w_kernel<<<(WFF2_CNT/4 + 255)/256, 256>>>(Wff2, rWff2, WFF2_CNT);

    embed_kernel<<<TOK, 256>>>(input_ids, word_emb, pos_emb, emb_ln_s, emb_ln_b, x);

    for (int l = 0; l < NLAYERS; l++){
        const float* wqkv = rWqkv + (size_t)l * HID * 3 * HID;
        const float* bq   = bqkv + (size_t)l * 3 * HID;
        const float* wo   = rWo   + (size_t)l * HID * HID;
        const float* bo_  = bo   + (size_t)l * HID;
        const float* s1   = ln1_s + (size_t)l * HID;
        const float* b1   = ln1_b + (size_t)l * HID;
        const float* w1   = rWff1 + (size_t)l * HID * FFN;
        const float* bf1  = bff1 + (size_t)l * FFN;
        const float* w2   = rWff2 + (size_t)l * FFN * HID;
        const float* bf2  = bff2 + (size_t)l * HID;
        const float* s2   = ln2_s + (size_t)l * HID;
        const float* b2   = ln2_b + (size_t)l * HID;

        gemm_tc<<<dim3(3 * HID / 128, TOK / 128), 256, GEMM_SMEM>>>(x, wqkv, bq, qkv, TOK, 3 * HID, HID, 0);
        attn3_kernel<<<dim3(SEQ / 128, NH, BSZ), 256, ATT_SMEM>>>(qkv, amask, attn);
        gemm_tc<<<dim3(HID / 128, TOK / 128), 256, GEMM_SMEM>>>(attn, wo, bo_, tmp, TOK, HID, HID, 0);
        ln_residual_kernel<<<TOK, 256>>>(x, tmp, s1, b1, h1);
        gemm_tc<<<dim3(FFN / 128, TOK / 128), 256, GEMM_SMEM>>>(h1, w1, bf1, ffn, TOK, FFN, HID, 1);
        gemm_tc<<<dim3(HID / 128, TOK / 128), 256, GEMM_SMEM>>>(ffn, w2, bf2, tmp, TOK, HID, FFN, 0);
        ln_residual_kernel<<<TOK, 256>>>(h1, tmp, s2, b2, x);
    }

    cls_kernel<<<TOK, 288>>>(x, Wcls, bcls, logits);
    crf_kernel<<<BSZ, 32>>>(logits, labels, crf_start, crf_end, crf_trans, res);
    int nlog = TOK * NT;
    finalize_kernel<<<(nlog + 256) / 256, 256>>>(res, logits, (float*)d_out, nlog);
}

// round 8
// speedup vs baseline: 10.6462x; 1.4593x over previous
#include <cuda_runtime.h>
#include <cuda_fp16.h>
#include <math.h>
#include <stdint.h>

#define BSZ 16
#define SEQ 256
#define HID 768
#define TOK (BSZ*SEQ)      // 4096
#define FFN 3072
#define NH 12
#define HD 64
#define NT 9
#define NLAYERS 6

#define WQKV_CNT (NLAYERS*HID*3*HID)
#define WO_CNT   (NLAYERS*HID*HID)
#define WFF1_CNT (NLAYERS*HID*FFN)
#define WFF2_CNT (NLAYERS*FFN*HID)
#define WTOT_CNT (WQKV_CNT+WO_CNT+WFF1_CNT+WFF2_CNT)

// ---------------- scratch ----------------
__device__ float  g_x[TOK*HID];
__device__ float  g_h1[TOK*HID];
__device__ float  g_tmp[TOK*HID];
__device__ float  g_qkv[TOK*3*HID];
__device__ float  g_logits[TOK*NT];
__device__ float  g_res[BSZ];
__device__ __half g_x16[TOK*HID];
__device__ __half g_h116[TOK*HID];
__device__ __half g_attn16[TOK*HID];
__device__ __half g_ffn16[(size_t)TOK*FFN];
__device__ __half g_wt16[(size_t)WTOT_CNT];   // transposed fp16 weights [N][K]

// ---------------- reductions ----------------
__device__ __forceinline__ float warpReduceSum(float v){
    #pragma unroll
    for (int o = 16; o; o >>= 1) v += __shfl_xor_sync(0xffffffffu, v, o);
    return v;
}
__device__ float blockReduceSum(float v, float* sh){
    __syncthreads();
    int lane = threadIdx.x & 31, wid = threadIdx.x >> 5;
    v = warpReduceSum(v);
    if (lane == 0) sh[wid] = v;
    __syncthreads();
    int nw = blockDim.x >> 5;
    v = (threadIdx.x < nw) ? sh[threadIdx.x] : 0.0f;
    if (wid == 0) v = warpReduceSum(v);
    if (threadIdx.x == 0) sh[0] = v;
    __syncthreads();
    return sh[0];
}

__device__ __forceinline__ float gelu_tanh(float x){
    float x3 = x * x * x;
    return 0.5f * x * (1.0f + tanhf(0.7978845608028654f * (x + 0.044715f * x3)));
}

// ---------------- mma / async helpers ----------------
__device__ __forceinline__ void mma_f16(float* c, const uint32_t* a, const uint32_t* b){
    asm volatile(
        "mma.sync.aligned.m16n8k16.row.col.f32.f16.f16.f32 "
        "{%0,%1,%2,%3},{%4,%5,%6,%7},{%8,%9},{%0,%1,%2,%3};"
        : "+f"(c[0]), "+f"(c[1]), "+f"(c[2]), "+f"(c[3])
        : "r"(a[0]), "r"(a[1]), "r"(a[2]), "r"(a[3]), "r"(b[0]), "r"(b[1]));
}
__device__ __forceinline__ void cpasync16(const void* smem, const void* g){
    uint32_t s = (uint32_t)__cvta_generic_to_shared(smem);
    asm volatile("cp.async.cg.shared.global [%0], [%1], 16;" :: "r"(s), "l"(g));
}
#define CP_COMMIT() asm volatile("cp.async.commit_group;")
#define CP_WAIT(n)  asm volatile("cp.async.wait_group %0;" :: "n"(n))

// ---------------- weight transpose + fp16 convert: W[K][N] -> Wt[N][K] --------
__global__ void transp_w(const float* __restrict__ src, __half* __restrict__ dst,
                         int K, int N){
    __shared__ float t[32][33];
    size_t off = (size_t)blockIdx.z * K * N;
    const float* s = src + off;
    __half* d = dst + off;
    int n0 = blockIdx.x * 32, k0 = blockIdx.y * 32;
    int tx = threadIdx.x, ty = threadIdx.y;
    #pragma unroll
    for (int i = 0; i < 4; i++){
        int k = k0 + ty + i * 8;
        t[ty + i * 8][tx] = s[(size_t)k * N + n0 + tx];
    }
    __syncthreads();
    #pragma unroll
    for (int i = 0; i < 4; i++){
        int n = n0 + ty + i * 8;
        d[(size_t)n * K + k0 + tx] = __float2half(t[tx][ty + i * 8]);
    }
}

// ---------------- embedding + LN (fp32 + fp16 outputs) ----------------
__global__ void embed_kernel(const int* __restrict__ ids,
                             const float* __restrict__ we,
                             const float* __restrict__ pe,
                             const float* __restrict__ gamma,
                             const float* __restrict__ beta,
                             float* __restrict__ out,
                             __half* __restrict__ out16){
    __shared__ float sh[32];
    int tok = blockIdx.x;
    int sI = tok % SEQ;
    int id = ids[tok];
    const float* wrow = we + (size_t)id * HID;
    const float* prow = pe + (size_t)sI * HID;
    float vals[3]; float lsum = 0.f;
    #pragma unroll
    for (int i = 0; i < 3; i++){
        int d = threadIdx.x + i * 256;
        float v = wrow[d] + prow[d];
        vals[i] = v; lsum += v;
    }
    float mean = blockReduceSum(lsum, sh) * (1.0f / HID);
    float lss = 0.f;
    #pragma unroll
    for (int i = 0; i < 3; i++){ float d0 = vals[i] - mean; lss += d0 * d0; }
    float var = blockReduceSum(lss, sh) * (1.0f / HID);
    float rstd = rsqrtf(var + 1e-12f);
    #pragma unroll
    for (int i = 0; i < 3; i++){
        int d = threadIdx.x + i * 256;
        float v = (vals[i] - mean) * rstd * gamma[d] + beta[d];
        out[(size_t)tok * HID + d] = v;
        out16[(size_t)tok * HID + d] = __float2half(v);
    }
}

// ---------------- residual + LN (fp32 out, optional fp16 copy) ----------------
__global__ void ln_residual_kernel(const float* __restrict__ a,
                                   const float* __restrict__ c,
                                   const float* __restrict__ gamma,
                                   const float* __restrict__ beta,
                                   float* __restrict__ out,
                                   __half* __restrict__ out16){
    __shared__ float sh[32];
    int tok = blockIdx.x;
    const float* ar = a + (size_t)tok * HID;
    const float* cr = c + (size_t)tok * HID;
    float vals[3]; float lsum = 0.f;
    #pragma unroll
    for (int i = 0; i < 3; i++){
        int d = threadIdx.x + i * 256;
        float v = ar[d] + cr[d];
        vals[i] = v; lsum += v;
    }
    float mean = blockReduceSum(lsum, sh) * (1.0f / HID);
    float lss = 0.f;
    #pragma unroll
    for (int i = 0; i < 3; i++){ float d0 = vals[i] - mean; lss += d0 * d0; }
    float var = blockReduceSum(lss, sh) * (1.0f / HID);
    float rstd = rsqrtf(var + 1e-12f);
    #pragma unroll
    for (int i = 0; i < 3; i++){
        int d = threadIdx.x + i * 256;
        float v = (vals[i] - mean) * rstd * gamma[d] + beta[d];
        out[(size_t)tok * HID + d] = v;
        out16[(size_t)tok * HID + d] = __float2half(v);
    }
}

// ---------------- fp16 TC GEMM: C[M,N] = A16[M,K] @ Wt16[N,K]^T + bias --------
// block 128x128, BK=32, 256 thr = 8 warps (4x2), warp tile 32x64, 2 smem stages.
// As/Bs: fp16, row stride 40 halves (80B) -> conflict-free fragment loads.
#define ASH 40
#define STG_H (128*ASH)            // halves per operand per stage
#define GEMM_SMEM (2 * 2 * STG_H * 2)   // bytes = 40960

__device__ __forceinline__ void g_fill(__half* as, __half* bs,
                                       const __half* __restrict__ A16,
                                       const __half* __restrict__ W16,
                                       int rowBase, int colBase, int K,
                                       int k0, int tid){
    int r = tid >> 1, c = (tid & 1) * 16;
    const __half* ag = A16 + (size_t)(rowBase + r) * K + k0 + c;
    __half* ad = as + r * ASH + c;
    cpasync16(ad, ag); cpasync16(ad + 8, ag + 8);
    const __half* bg = W16 + (size_t)(colBase + r) * K + k0 + c;
    __half* bd = bs + r * ASH + c;
    cpasync16(bd, bg); cpasync16(bd + 8, bg + 8);
}

__global__ void __launch_bounds__(256, 2)
gemm_h(const __half* __restrict__ A16,
       const __half* __restrict__ W16,
       const float* __restrict__ bias,
       float* __restrict__ C32,
       __half* __restrict__ C16,
       int M, int N, int K, int act){   // act: 0 = fp32 out, 1 = gelu + fp16 out
    extern __shared__ char smraw[];
    __half* sm = (__half*)smraw;
    __half* As[2] = { sm,             sm + 2*STG_H };
    __half* Bs[2] = { sm + STG_H,     sm + 3*STG_H };

    int tid = threadIdx.x;
    int wid = tid >> 5, lane = tid & 31;
    int warpRow = wid >> 1, warpCol = wid & 1;
    int gid = lane >> 2, tig = lane & 3;
    int rowBase = blockIdx.y * 128, colBase = blockIdx.x * 128;

    float acc[2][8][4];
    #pragma unroll
    for (int mi = 0; mi < 2; mi++)
        #pragma unroll
        for (int ni = 0; ni < 8; ni++)
            #pragma unroll
            for (int j = 0; j < 4; j++) acc[mi][ni][j] = 0.f;

    int ntile = K >> 5;

    g_fill(As[0], Bs[0], A16, W16, rowBase, colBase, K, 0, tid);
    CP_COMMIT();

    for (int t = 0; t < ntile; t++){
        if (t + 1 < ntile){
            g_fill(As[(t+1)&1], Bs[(t+1)&1], A16, W16, rowBase, colBase, K, (t+1) << 5, tid);
            CP_COMMIT();
            CP_WAIT(1);
        } else {
            CP_WAIT(0);
        }
        __syncthreads();

        const __half* as = As[t & 1];
        const __half* bs = Bs[t & 1];
        #pragma unroll
        for (int sl = 0; sl < 2; sl++){
            int kb = sl * 16;
            uint32_t af[2][4], bf[8][2];
            #pragma unroll
            for (int mi = 0; mi < 2; mi++){
                int m0 = warpRow * 32 + mi * 16;
                const __half* r0 = as + (m0 + gid) * ASH + kb + tig * 2;
                const __half* r1 = as + (m0 + gid + 8) * ASH + kb + tig * 2;
                af[mi][0] = *(const uint32_t*)r0;
                af[mi][1] = *(const uint32_t*)r1;
                af[mi][2] = *(const uint32_t*)(r0 + 8);
                af[mi][3] = *(const uint32_t*)(r1 + 8);
            }
            #pragma unroll
            for (int ni = 0; ni < 8; ni++){
                int n0 = warpCol * 64 + ni * 8;
                const __half* bp = bs + (n0 + gid) * ASH + kb + tig * 2;
                bf[ni][0] = *(const uint32_t*)bp;
                bf[ni][1] = *(const uint32_t*)(bp + 8);
            }
            #pragma unroll
            for (int mi = 0; mi < 2; mi++)
                #pragma unroll
                for (int ni = 0; ni < 8; ni++)
                    mma_f16(acc[mi][ni], af[mi], bf[ni]);
        }
        __syncthreads();
    }

    #pragma unroll
    for (int mi = 0; mi < 2; mi++){
        int r0 = rowBase + warpRow * 32 + mi * 16 + gid;
        #pragma unroll
        for (int ni = 0; ni < 8; ni++){
            int cc = colBase + warpCol * 64 + ni * 8 + tig * 2;
            float b0 = bias[cc], b1 = bias[cc + 1];
            float v0 = acc[mi][ni][0] + b0, v1 = acc[mi][ni][1] + b1;
            float v2 = acc[mi][ni][2] + b0, v3 = acc[mi][ni][3] + b1;
            if (act == 1){
                v0 = gelu_tanh(v0); v1 = gelu_tanh(v1);
                v2 = gelu_tanh(v2); v3 = gelu_tanh(v3);
                *(__half2*)&C16[(size_t)r0 * N + cc]       = __floats2half2_rn(v0, v1);
                *(__half2*)&C16[(size_t)(r0 + 8) * N + cc] = __floats2half2_rn(v2, v3);
            } else {
                *(float2*)&C32[(size_t)r0 * N + cc]       = make_float2(v0, v1);
                *(float2*)&C32[(size_t)(r0 + 8) * N + cc] = make_float2(v2, v3);
            }
        }
    }
}

// ---------------- attention: fp16 tensor-core flash attention ------------------
// block = (128 queries, head, batch), 256 thr = 8 warps, warp owns 16 queries.
// smem halves: Qs[128][72] | Ks[64][72] ([key][d]) | Vt[64][72] ([d][key]) |
//              Pw[8][16][72] ; then bs[256] floats.
#define AQ 72
#define ATT_H (128*AQ + 64*AQ + 64*AQ + 8*16*AQ)
#define ATT_SMEM (ATT_H*2 + 256*4)
__global__ void __launch_bounds__(256, 2)
attn4_kernel(const float* __restrict__ qkv,
             const int* __restrict__ amask,
             __half* __restrict__ out16){
    extern __shared__ char smraw[];
    __half* Qs = (__half*)smraw;
    __half* Ks = Qs + 128 * AQ;
    __half* Vt = Ks + 64 * AQ;
    __half* Pa = Vt + 64 * AQ;
    float*  bsm = (float*)(smraw + ATT_H * 2);
    int tid = threadIdx.x, w = tid >> 5, lane = tid & 31;
    int gid = lane >> 2, tig = lane & 3;
    int qb = blockIdx.x * 128, h = blockIdx.y, b = blockIdx.z;
    const size_t rs = 3 * HID;
    const float* base = qkv + (size_t)b * SEQ * rs;
    __half* Pw = Pa + w * 16 * AQ;
    int m0 = w * 16;

    bsm[tid] = (1.0f - (float)amask[b * SEQ + tid]) * -1e9f;

    // load Q tile, pre-scaled, fp16
    {
        int r = tid >> 1, c0 = (tid & 1) * 32;
        const float* src = base + (size_t)(qb + r) * rs + h * HD + c0;
        __half* dst = Qs + r * AQ + c0;
        #pragma unroll
        for (int j = 0; j < 8; j++){
            float4 v = *(const float4*)(src + j * 4);
            *(__half2*)(dst + j*4)     = __floats2half2_rn(v.x * 0.125f, v.y * 0.125f);
            *(__half2*)(dst + j*4 + 2) = __floats2half2_rn(v.z * 0.125f, v.w * 0.125f);
        }
    }

    float of[8][4];
    #pragma unroll
    for (int ni = 0; ni < 8; ni++)
        #pragma unroll
        for (int j = 0; j < 4; j++) of[ni][j] = 0.f;
    float mrow0 = -1e30f, mrow1 = -1e30f, lrow0 = 0.f, lrow1 = 0.f;

    for (int c = 0; c < 4; c++){
        __syncthreads();
        {   // K chunk natural [key][d], V chunk transposed [d][key], fp16
            int k = tid >> 2, d0 = (tid & 3) * 16;
            const float* ks = base + (size_t)(c * 64 + k) * rs + HID + h * HD + d0;
            const float* vs = base + (size_t)(c * 64 + k) * rs + 2 * HID + h * HD + d0;
            #pragma unroll
            for (int j = 0; j < 4; j++){
                float4 kv = *(const float4*)(ks + j * 4);
                *(__half2*)(Ks + k * AQ + d0 + j*4)     = __floats2half2_rn(kv.x, kv.y);
                *(__half2*)(Ks + k * AQ + d0 + j*4 + 2) = __floats2half2_rn(kv.z, kv.w);
                float4 vv = *(const float4*)(vs + j * 4);
                Vt[(d0 + j*4 + 0) * AQ + k] = __float2half(vv.x);
                Vt[(d0 + j*4 + 1) * AQ + k] = __float2half(vv.y);
                Vt[(d0 + j*4 + 2) * AQ + k] = __float2half(vv.z);
                Vt[(d0 + j*4 + 3) * AQ + k] = __float2half(vv.w);
            }
        }
        __syncthreads();

        // ---- S = Q @ K^T (4 k16 slices over d=64) ----
        float sc[8][4];
        #pragma unroll
        for (int ni = 0; ni < 8; ni++)
            #pragma unroll
            for (int j = 0; j < 4; j++) sc[ni][j] = 0.f;
        #pragma unroll
        for (int sl = 0; sl < 4; sl++){
            int kb = sl * 16;
            uint32_t a[4];
            const __half* q0 = Qs + (m0 + gid) * AQ + kb + tig * 2;
            const __half* q1 = Qs + (m0 + gid + 8) * AQ + kb + tig * 2;
            a[0] = *(const uint32_t*)q0;
            a[1] = *(const uint32_t*)q1;
            a[2] = *(const uint32_t*)(q0 + 8);
            a[3] = *(const uint32_t*)(q1 + 8);
            #pragma unroll
            for (int ni = 0; ni < 8; ni++){
                int n0 = ni * 8;
                const __half* bp = Ks + (n0 + gid) * AQ + kb + tig * 2;
                uint32_t bf[2];
                bf[0] = *(const uint32_t*)bp;
                bf[1] = *(const uint32_t*)(bp + 8);
                mma_f16(sc[ni], a, bf);
            }
        }

        // ---- online softmax ----
        float mx0 = -1e30f, mx1 = -1e30f;
        #pragma unroll
        for (int ni = 0; ni < 8; ni++){
            int key = c * 64 + ni * 8 + tig * 2;
            float b0 = bsm[key], b1 = bsm[key + 1];
            sc[ni][0] += b0; sc[ni][1] += b1;
            sc[ni][2] += b0; sc[ni][3] += b1;
            mx0 = fmaxf(mx0, fmaxf(sc[ni][0], sc[ni][1]));
            mx1 = fmaxf(mx1, fmaxf(sc[ni][2], sc[ni][3]));
        }
        mx0 = fmaxf(mx0, __shfl_xor_sync(0xffffffffu, mx0, 1));
        mx0 = fmaxf(mx0, __shfl_xor_sync(0xffffffffu, mx0, 2));
        mx1 = fmaxf(mx1, __shfl_xor_sync(0xffffffffu, mx1, 1));
        mx1 = fmaxf(mx1, __shfl_xor_sync(0xffffffffu, mx1, 2));
        float nm0 = fmaxf(mrow0, mx0), nm1 = fmaxf(mrow1, mx1);
        float corr0 = __expf(mrow0 - nm0), corr1 = __expf(mrow1 - nm1);
        float sum0 = 0.f, sum1 = 0.f;
        #pragma unroll
        for (int ni = 0; ni < 8; ni++){
            float p0 = __expf(sc[ni][0] - nm0);
            float p1 = __expf(sc[ni][1] - nm0);
            float p2 = __expf(sc[ni][2] - nm1);
            float p3 = __expf(sc[ni][3] - nm1);
            sum0 += p0 + p1; sum1 += p2 + p3;
            int n0 = ni * 8 + tig * 2;
            *(__half2*)(Pw + gid * AQ + n0)       = __floats2half2_rn(p0, p1);
            *(__half2*)(Pw + (gid + 8) * AQ + n0) = __floats2half2_rn(p2, p3);
        }
        sum0 += __shfl_xor_sync(0xffffffffu, sum0, 1);
        sum0 += __shfl_xor_sync(0xffffffffu, sum0, 2);
        sum1 += __shfl_xor_sync(0xffffffffu, sum1, 1);
        sum1 += __shfl_xor_sync(0xffffffffu, sum1, 2);
        lrow0 = lrow0 * corr0 + sum0;
        lrow1 = lrow1 * corr1 + sum1;
        mrow0 = nm0; mrow1 = nm1;
        #pragma unroll
        for (int ni = 0; ni < 8; ni++){
            of[ni][0] *= corr0; of[ni][1] *= corr0;
            of[ni][2] *= corr1; of[ni][3] *= corr1;
        }
        __syncwarp();

        // ---- O += P @ V (A = Pw fp16, B = Vt [d][key]) ----
        #pragma unroll
        for (int sl = 0; sl < 4; sl++){
            int kb = sl * 16;
            uint32_t a[4];
            const __half* p0 = Pw + gid * AQ + kb + tig * 2;
            const __half* p1 = Pw + (gid + 8) * AQ + kb + tig * 2;
            a[0] = *(const uint32_t*)p0;
            a[1] = *(const uint32_t*)p1;
            a[2] = *(const uint32_t*)(p0 + 8);
            a[3] = *(const uint32_t*)(p1 + 8);
            #pragma unroll
            for (int ni = 0; ni < 8; ni++){
                int n0 = ni * 8;
                const __half* bp = Vt + (n0 + gid) * AQ + kb + tig * 2;
                uint32_t bf[2];
                bf[0] = *(const uint32_t*)bp;
                bf[1] = *(const uint32_t*)(bp + 8);
                mma_f16(of[ni], a, bf);
            }
        }
        __syncwarp();
    }

    // ---- normalize + write fp16 ----
    float inv0 = 1.0f / lrow0, inv1 = 1.0f / lrow1;
    int q0 = qb + m0 + gid, q1 = q0 + 8;
    #pragma unroll
    for (int ni = 0; ni < 8; ni++){
        int d = ni * 8 + tig * 2;
        *(__half2*)&out16[(size_t)(b * SEQ + q0) * HID + h * HD + d] =
            __floats2half2_rn(of[ni][0] * inv0, of[ni][1] * inv0);
        *(__half2*)&out16[(size_t)(b * SEQ + q1) * HID + h * HD + d] =
            __floats2half2_rn(of[ni][2] * inv1, of[ni][3] * inv1);
    }
}

// ---------------- classifier ----------------
__global__ void cls_kernel(const float* __restrict__ x,
                           const float* __restrict__ W,
                           const float* __restrict__ bias,
                           float* __restrict__ logits){
    __shared__ float xs[HID];
    int tok = blockIdx.x;
    for (int d = threadIdx.x; d < HID; d += blockDim.x)
        xs[d] = x[(size_t)tok * HID + d];
    __syncthreads();
    int w = threadIdx.x >> 5, lane = threadIdx.x & 31;
    float acc = 0.f;
    for (int d = lane; d < HID; d += 32)
        acc = fmaf(xs[d], W[d * NT + w], acc);
    acc = warpReduceSum(acc);
    if (lane == 0) logits[tok * NT + w] = acc + bias[w];
}

// ---------------- CRF ----------------
__global__ void crf_kernel(const float* __restrict__ logits,
                           const int* __restrict__ labels,
                           const float* __restrict__ cstart,
                           const float* __restrict__ cend,
                           const float* __restrict__ ctrans,
                           float* __restrict__ res){
    __shared__ float score[NT];
    __shared__ float tr[NT * NT];
    __shared__ float st[NT], en[NT];
    int b = blockIdx.x, tid = threadIdx.x;
    for (int i = tid; i < NT * NT; i += 32) tr[i] = ctrans[i];
    if (tid < NT){ st[tid] = cstart[tid]; en[tid] = cend[tid]; }
    const float* lg = logits + (size_t)b * SEQ * NT;
    const int* lab = labels + b * SEQ;
    if (tid < NT) score[tid] = st[tid] + lg[tid];
    __syncwarp();
    for (int s = 1; s < SEQ; s++){
        float nxt = 0.f;
        if (tid < NT){
            float m = -INFINITY;
            #pragma unroll
            for (int i = 0; i < NT; i++) m = fmaxf(m, score[i] + tr[i * NT + tid]);
            float sum = 0.f;
            #pragma unroll
            for (int i = 0; i < NT; i++) sum += expf(score[i] + tr[i * NT + tid] - m);
            nxt = m + logf(sum) + lg[s * NT + tid];
        }
        bool msk = (lab[s] != -100);
        __syncwarp();
        if (tid < NT && msk) score[tid] = nxt;
        __syncwarp();
    }
    if (tid == 0){
        float m = -INFINITY;
        for (int t = 0; t < NT; t++) m = fmaxf(m, score[t] + en[t]);
        float sum = 0.f;
        for (int t = 0; t < NT; t++) sum += expf(score[t] + en[t] - m);
        float denom = m + logf(sum);
        int l0 = lab[0];
        int tag_prev = (l0 == -100) ? 0 : l0;
        float num = st[tag_prev] + lg[tag_prev];
        int cnt = 1;
        for (int s = 1; s < SEQ; s++){
            int ls = lab[s];
            bool msk = (ls != -100);
            int tg = msk ? ls : 0;
            if (msk){
                num += tr[tag_prev * NT + tg] + lg[s * NT + tg];
                cnt++;
            }
            tag_prev = tg;
        }
        int seq_end = cnt - 1;
        int le = lab[seq_end];
        int last_tag = (le == -100) ? 0 : le;
        num += en[last_tag];
        res[b] = num - denom;
    }
}

// ---------------- finalize ----------------
__global__ void finalize_kernel(const float* __restrict__ res,
                                const float* __restrict__ logits,
                                float* __restrict__ out, int nlog){
    int idx = blockIdx.x * blockDim.x + threadIdx.x;
    if (idx == 0){
        float s = 0.f;
        for (int b = 0; b < BSZ; b++) s += res[b];
        out[0] = -s / BSZ;
    }
    if (idx < nlog) out[1 + idx] = logits[idx];
}

// ---------------- launch ----------------
extern "C" void kernel_launch(void* const* d_in, const int* in_sizes, int n_in,
                              void* d_out, int out_size){
    const int*   input_ids = (const int*)  d_in[0];
    const int*   amask     = (const int*)  d_in[1];
    const int*   labels    = (const int*)  d_in[2];
    const float* word_emb  = (const float*)d_in[3];
    const float* pos_emb   = (const float*)d_in[4];
    const float* emb_ln_s  = (const float*)d_in[5];
    const float* emb_ln_b  = (const float*)d_in[6];
    const float* Wqkv      = (const float*)d_in[7];
    const float* bqkv      = (const float*)d_in[8];
    const float* Wo        = (const float*)d_in[9];
    const float* bo        = (const float*)d_in[10];
    const float* ln1_s     = (const float*)d_in[11];
    const float* ln1_b     = (const float*)d_in[12];
    const float* Wff1      = (const float*)d_in[13];
    const float* bff1      = (const float*)d_in[14];
    const float* Wff2      = (const float*)d_in[15];
    const float* bff2      = (const float*)d_in[16];
    const float* ln2_s     = (const float*)d_in[17];
    const float* ln2_b     = (const float*)d_in[18];
    const float* Wcls      = (const float*)d_in[19];
    const float* bcls      = (const float*)d_in[20];
    const float* crf_start = (const float*)d_in[21];
    const float* crf_end   = (const float*)d_in[22];
    const float* crf_trans = (const float*)d_in[23];

    float *x, *h1, *tmp, *qkv, *logits, *res;
    __half *x16, *h116, *attn16, *ffn16, *wt16;
    cudaGetSymbolAddress((void**)&x,      g_x);
    cudaGetSymbolAddress((void**)&h1,     g_h1);
    cudaGetSymbolAddress((void**)&tmp,    g_tmp);
    cudaGetSymbolAddress((void**)&qkv,    g_qkv);
    cudaGetSymbolAddress((void**)&logits, g_logits);
    cudaGetSymbolAddress((void**)&res,    g_res);
    cudaGetSymbolAddress((void**)&x16,    g_x16);
    cudaGetSymbolAddress((void**)&h116,   g_h116);
    cudaGetSymbolAddress((void**)&attn16, g_attn16);
    cudaGetSymbolAddress((void**)&ffn16,  g_ffn16);
    cudaGetSymbolAddress((void**)&wt16,   g_wt16);

    __half* tWqkv = wt16;
    __half* tWo   = tWqkv + WQKV_CNT;
    __half* tWff1 = tWo   + WO_CNT;
    __half* tWff2 = tWff1 + WFF1_CNT;

    static int smem_set = 0;
    if (!smem_set){
        cudaFuncSetAttribute(attn4_kernel,
                             cudaFuncAttributeMaxDynamicSharedMemorySize, ATT_SMEM);
        cudaFuncSetAttribute(gemm_h,
                             cudaFuncAttributeMaxDynamicSharedMemorySize, GEMM_SMEM);
        smem_set = 1;
    }

    dim3 t328(32, 8);
    transp_w<<<dim3(3*HID/32, HID/32, NLAYERS), t328>>>(Wqkv, tWqkv, HID, 3*HID);
    transp_w<<<dim3(HID/32,   HID/32, NLAYERS), t328>>>(Wo,   tWo,   HID, HID);
    transp_w<<<dim3(FFN/32,   HID/32, NLAYERS), t328>>>(Wff1, tWff1, HID, FFN);
    transp_w<<<dim3(HID/32,   FFN/32, NLAYERS), t328>>>(Wff2, tWff2, FFN, HID);

    embed_kernel<<<TOK, 256>>>(input_ids, word_emb, pos_emb, emb_ln_s, emb_ln_b, x, x16);

    for (int l = 0; l < NLAYERS; l++){
        const __half* wqkv = tWqkv + (size_t)l * HID * 3 * HID;
        const float* bq   = bqkv + (size_t)l * 3 * HID;
        const __half* wo  = tWo   + (size_t)l * HID * HID;
        const float* bo_  = bo   + (size_t)l * HID;
        const float* s1   = ln1_s + (size_t)l * HID;
        const float* b1   = ln1_b + (size_t)l * HID;
        const __half* w1  = tWff1 + (size_t)l * HID * FFN;
        const float* bf1  = bff1 + (size_t)l * FFN;
        const __half* w2  = tWff2 + (size_t)l * FFN * HID;
        const float* bf2  = bff2 + (size_t)l * HID;
        const float* s2   = ln2_s + (size_t)l * HID;
        const float* b2   = ln2_b + (size_t)l * HID;

        // QKV: A = x16, out fp32 qkv
        gemm_h<<<dim3(3*HID/128, TOK/128), 256, GEMM_SMEM>>>(x16, wqkv, bq, qkv, nullptr, TOK, 3*HID, HID, 0);
        // attention -> attn16 (fp16)
        attn4_kernel<<<dim3(SEQ/128, NH, BSZ), 256, ATT_SMEM>>>(qkv, amask, attn16);
        // O-proj: A = attn16, out fp32 tmp
        gemm_h<<<dim3(HID/128, TOK/128), 256, GEMM_SMEM>>>(attn16, wo, bo_, tmp, nullptr, TOK, HID, HID, 0);
        // h1 = LN(x + tmp) -> fp32 + fp16
        ln_residual_kernel<<<TOK, 256>>>(x, tmp, s1, b1, h1, h116);
        // FFN1: A = h116, gelu -> ffn16 (fp16)
        gemm_h<<<dim3(FFN/128, TOK/128), 256, GEMM_SMEM>>>(h116, w1, bf1, nullptr, ffn16, TOK, FFN, HID, 1);
        // FFN2: A = ffn16, out fp32 tmp
        gemm_h<<<dim3(HID/128, TOK/128), 256, GEMM_SMEM>>>(ffn16, w2, bf2, tmp, nullptr, TOK, HID, FFN, 0);
        // x = LN(h1 + tmp) -> fp32 + fp16
        ln_residual_kernel<<<TOK, 256>>>(h1, tmp, s2, b2, x, x16);
    }

    cls_kernel<<<TOK, 288>>>(x, Wcls, bcls, logits);
    crf_kernel<<<BSZ, 32>>>(logits, labels, crf_start, crf_end, crf_trans, res);
    int nlog = TOK * NT;
    finalize_kernel<<<(nlog + 256) / 256, 256>>>(res, logits, (float*)d_out, nlog);
}